// round 15
// baseline (speedup 1.0000x reference)
#include <cuda_runtime.h>
#include <cstdint>

#define NF 32
#define LL 8
#define HDIM 256
#define KBINS 8
#define PP 25
#define NP 800
#define MT 64
#define NTHREADS 512
#define MSTR 72         // activation stride [k][m]: mod 32 = 8 -> conflict-free mma frags
#define WSTR 264        // padded tf32 conditioner-weight row stride (mod 32 = 8)
#define WOSTR 424       // padded tf32 W_out row stride (mod 32 = 8), 416 cols used
#define PSTR 401        // params buffer stride

#define RMINF (-10.0f)
#define RMAXF (10.0f)
#define MINBIN (1e-4f)
#define MINSLOPE (1e-4f)

#define CTILE  ((unsigned int)(32 * WSTR * 4))    // 33792 B (conditioner 32-row tile)
#define WOTILE ((unsigned int)(16 * WOSTR * 4))   // 27136 B (W_out 16-row tile)
#define SLOTB  CTILE                               // slot byte stride (max payload)
#define SLOTF  (32 * WSTR)                         // slot stride in floats

typedef unsigned long long u64;

__device__ __align__(16) float g_wpad[(size_t)LL * 4 * HDIM * WSTR];
__device__ __align__(16) float g_wopad[(size_t)LL * HDIM * WOSTR];
__device__ __align__(16) float g_bopad[LL * 416];
__device__ __align__(16) float g_wf[LL * 16 * HDIM];   // fp32 fused W_in@W1a
__device__ __align__(16) float g_bf[LL * HDIM];        // fp32 fused b_in@W1a + b1a

__device__ __forceinline__ u64 pack2(float lo, float hi) {
    u64 r; asm("mov.b64 %0, {%1,%2};" : "=l"(r) : "f"(lo), "f"(hi)); return r;
}
__device__ __forceinline__ float2 unpack2(u64 v) {
    float2 r; asm("mov.b64 {%0,%1}, %2;" : "=f"(r.x), "=f"(r.y) : "l"(v)); return r;
}
__device__ __forceinline__ void fma2(u64& d, u64 a, u64 b) {
    asm("fma.rn.f32x2 %0, %1, %2, %0;" : "+l"(d) : "l"(a), "l"(b));
}
__device__ __forceinline__ float rna_tf32(float v) {
    unsigned int u; asm("cvt.rna.tf32.f32 %0, %1;" : "=r"(u) : "f"(v));
    return __uint_as_float(u);
}
__device__ __forceinline__ void mma_tf32(float* d,
                                         unsigned int a0, unsigned int a1,
                                         unsigned int a2, unsigned int a3,
                                         unsigned int b0, unsigned int b1) {
    asm("mma.sync.aligned.m16n8k8.row.col.f32.tf32.tf32.f32 "
        "{%0,%1,%2,%3}, {%4,%5,%6,%7}, {%8,%9}, {%0,%1,%2,%3};"
        : "+f"(d[0]), "+f"(d[1]), "+f"(d[2]), "+f"(d[3])
        : "r"(a0), "r"(a1), "r"(a2), "r"(a3), "r"(b0), "r"(b1));
}

// ---- mbarrier + 1D bulk-async helpers ----
__device__ __forceinline__ void mbar_init(unsigned int mbar, unsigned int cnt) {
    asm volatile("mbarrier.init.shared.b64 [%0], %1;" :: "r"(mbar), "r"(cnt) : "memory");
}
__device__ __forceinline__ void mbar_expect_tx(unsigned int mbar, unsigned int bytes) {
    asm volatile("mbarrier.arrive.expect_tx.shared.b64 _, [%0], %1;"
                 :: "r"(mbar), "r"(bytes) : "memory");
}
__device__ __forceinline__ void mbar_arrive(unsigned int mbar) {
    asm volatile("mbarrier.arrive.shared.b64 _, [%0];" :: "r"(mbar) : "memory");
}
__device__ __forceinline__ void bulk_g2s(unsigned int dst, const void* src,
                                         unsigned int bytes, unsigned int mbar) {
    asm volatile("cp.async.bulk.shared::cluster.global.mbarrier::complete_tx::bytes "
                 "[%0], [%1], %2, [%3];"
                 :: "r"(dst), "l"(src), "r"(bytes), "r"(mbar) : "memory");
}
__device__ __forceinline__ void mbar_wait(unsigned int mbar, int parity) {
    unsigned int done;
    asm volatile(
        "{\n\t.reg .pred p;\n\t"
        "mbarrier.try_wait.parity.acquire.cta.shared::cta.b64 p, [%1], %2;\n\t"
        "selp.b32 %0, 1, 0, p;\n\t}"
        : "=r"(done) : "r"(mbar), "r"(parity) : "memory");
    if (!done) {
        asm volatile(
            "{\n\t.reg .pred P1;\n\t"
            "WAIT_LOOP_%=:\n\t"
            "mbarrier.try_wait.parity.acquire.cta.shared::cta.b64 P1, [%0], %1, 0x989680;\n\t"
            "@P1 bra.uni WAIT_DONE_%=;\n\t"
            "bra.uni WAIT_LOOP_%=;\n\t"
            "WAIT_DONE_%=:\n\t}"
            :: "r"(mbar), "r"(parity) : "memory");
    }
}

// ---------------------------------------------------------------------------
// Prep kernels
// ---------------------------------------------------------------------------
extern "C" __global__ void prep_weights(const float* __restrict__ W1a,
                                        const float* __restrict__ W1b,
                                        const float* __restrict__ W2a,
                                        const float* __restrict__ W2b)
{
    long long idx = (long long)blockIdx.x * blockDim.x + threadIdx.x;
    const long long total = (long long)LL * 4 * HDIM * WSTR;
    if (idx >= total) return;
    int col = (int)(idx % WSTR);
    long long t = idx / WSTR;
    int row = (int)(t % HDIM);
    int mat = (int)(t / HDIM);
    int i = mat >> 2, j = mat & 3;
    const float* src = (j == 0 ? W1a : j == 1 ? W1b : j == 2 ? W2a : W2b);
    float v = (col < HDIM) ? src[(long long)i * HDIM * HDIM + row * HDIM + col] : 0.f;
    g_wpad[idx] = rna_tf32(v);
}

// Pack W_out: layer i, dim j (actual n=2j+(i&1)) occupies cols [25j, 25j+25), pad to 416.
extern "C" __global__ void prep_wout(const float* __restrict__ Wo,
                                     const float* __restrict__ bo)
{
    long long idx = (long long)blockIdx.x * blockDim.x + threadIdx.x;
    const long long totalW = (long long)LL * HDIM * WOSTR;
    if (idx < totalW) {
        int col = (int)(idx % WOSTR);
        long long t = idx / WOSTR;
        int row = (int)(t % HDIM);
        int i = (int)(t / HDIM);
        int toff = i & 1;
        float v = 0.f;
        if (col < 400) {
            int j = col / 25, p = col - j * 25;
            v = Wo[(long long)i * HDIM * NP + (long long)row * NP + (2 * j + toff) * PP + p];
        }
        g_wopad[idx] = rna_tf32(v);
    }
    if (idx < LL * 416) {
        int i = (int)(idx / 416), col = (int)(idx % 416);
        int toff = i & 1;
        float v = 0.f;
        if (col < 400) {
            int j = col / 25, p = col - j * 25;
            v = bo[i * NP + (2 * j + toff) * PP + p];
        }
        g_bopad[idx] = v;
    }
}

extern "C" __global__ void prep_fused(const float* __restrict__ W_in,
                                      const float* __restrict__ b_in,
                                      const float* __restrict__ W1a,
                                      const float* __restrict__ b1a)
{
    int idx = blockIdx.x * blockDim.x + threadIdx.x;
    const int totalW = LL * 16 * HDIM;
    if (idx < totalW) {
        int c = idx % HDIM;
        int t = idx / HDIM;
        int k = t % 16;
        int i = t / 16;
        int koff = (i & 1) ? 0 : 1;
        int n = 2 * k + koff;
        const float* wi = W_in + ((size_t)i * NF + n) * HDIM;
        const float* wa = W1a + (size_t)i * HDIM * HDIM + c;
        float s = 0.f;
        for (int j = 0; j < HDIM; j++) s = fmaf(wi[j], wa[(size_t)j * HDIM], s);
        g_wf[idx] = s;
    }
    if (idx < LL * HDIM) {
        int c = idx % HDIM;
        int i = idx / HDIM;
        const float* bi = b_in + i * HDIM;
        const float* wa = W1a + (size_t)i * HDIM * HDIM + c;
        float s = b1a[i * HDIM + c];
        for (int j = 0; j < HDIM; j++) s = fmaf(bi[j], wa[(size_t)j * HDIM], s);
        g_bf[idx] = s;
    }
}

// ---------------------------------------------------------------------------
// mmIn (16 warps): warp -> 16 cols, lane -> 2 rows.
// ---------------------------------------------------------------------------
template <int STORE, int RSTRIDE>
__device__ __forceinline__ void mmIn(const float* __restrict__ W,
                                     const float* __restrict__ bi,
                                     const float* __restrict__ xsT,
                                     float* __restrict__ DT,
                                     int warpid, int lane, int rowOff)
{
    const int cb = warpid << 4;
    const int m0 = lane << 1;
    u64 acc[2][8];
    const ulonglong2* bp = reinterpret_cast<const ulonglong2*>(bi + cb);
#pragma unroll
    for (int q = 0; q < 4; q++) {
        ulonglong2 b = bp[q];
        acc[0][2*q] = b.x; acc[0][2*q+1] = b.y;
        acc[1][2*q] = b.x; acc[1][2*q+1] = b.y;
    }
#pragma unroll
    for (int k = 0; k < 16; k++) {
        const int n = 2*k + rowOff;
        const int wr = (RSTRIDE == 2) ? n : k;
        float2 av = *reinterpret_cast<const float2*>(xsT + n*MSTR + m0);
        u64 a0 = pack2(av.x, av.x);
        u64 a1 = pack2(av.y, av.y);
        const ulonglong2* wp = reinterpret_cast<const ulonglong2*>(W + wr*HDIM + cb);
#pragma unroll
        for (int q = 0; q < 4; q++) {
            ulonglong2 w = wp[q];
            fma2(acc[0][2*q],   a0, w.x);
            fma2(acc[0][2*q+1], a0, w.y);
            fma2(acc[1][2*q],   a1, w.x);
            fma2(acc[1][2*q+1], a1, w.y);
        }
    }
#pragma unroll
    for (int q = 0; q < 8; q++) {
        float2 r0 = unpack2(acc[0][q]);
        float2 r1 = unpack2(acc[1][q]);
        float v00 = r0.x, v10 = r1.x, v01 = r0.y, v11 = r1.y;
        if (STORE == 1) {
            v00 = rna_tf32(fmaxf(v00, 0.f)); v10 = rna_tf32(fmaxf(v10, 0.f));
            v01 = rna_tf32(fmaxf(v01, 0.f)); v11 = rna_tf32(fmaxf(v11, 0.f));
        }
        *reinterpret_cast<float2*>(DT + (cb + 2*q)*MSTR + m0)     = make_float2(v00, v10);
        *reinterpret_cast<float2*>(DT + (cb + 2*q + 1)*MSTR + m0) = make_float2(v01, v11);
    }
}

// ---------------------------------------------------------------------------
// mm256 tf32 mma, m32n32 warp tiles (2m x 8n). 32-row k-tiles (8 rendezvous).
// ALL A fragments of the k-tile preloaded BEFORE the full-barrier wait
// (AT stable for the whole GEMM) -> post-wait path is B loads + HMMA only.
// MODE 1: D=rna(relu); 2: D=rna(D+relu); 3: D=rna(relu(D+relu)).
// ---------------------------------------------------------------------------
template <int MODE>
__device__ __forceinline__ void mm256t(const float* __restrict__ Wp,
                                       const float* __restrict__ bias,
                                       const float* __restrict__ AT,
                                       float* __restrict__ DT,
                                       const float* __restrict__ wbuf, unsigned int wsm,
                                       const float* __restrict__ nextW,
                                       unsigned int nextBytes, int nextT1Off,
                                       unsigned int fb0, unsigned int fb1,
                                       unsigned int eb0, unsigned int eb1,
                                       int& pf0, int& pf1, int& pe0, int& pe1,
                                       int warpid, int lane, int tid)
{
    const int mwp = warpid & 1, nw = warpid >> 1;
    const int m0 = mwp << 5;
    const int n0w = nw << 5;
    const int r = lane >> 2, c = lane & 3;

    float d[2][4][4];
#pragma unroll
    for (int nt = 0; nt < 4; nt++) {
        float b0 = bias[n0w + nt*8 + 2*c];
        float b1 = bias[n0w + nt*8 + 2*c + 1];
#pragma unroll
        for (int mf = 0; mf < 2; mf++) {
            d[mf][nt][0] = b0; d[mf][nt][1] = b1;
            d[mf][nt][2] = b0; d[mf][nt][3] = b1;
        }
    }

#pragma unroll 1
    for (int kb = 0; kb < 8; kb++) {
        const int s = kb & 1;
        // preload ALL A fragments of this k-tile before the wait
        unsigned int apre[4][2][4];
#pragma unroll
        for (int ks = 0; ks < 4; ks++) {
            const int k0 = kb * 32 + ks * 8;
#pragma unroll
            for (int mf = 0; mf < 2; mf++) {
                const float* Ab = AT + (k0 + c) * MSTR + m0 + mf * 16 + r;
                apre[ks][mf][0] = __float_as_uint(Ab[0]);
                apre[ks][mf][1] = __float_as_uint(Ab[8]);
                apre[ks][mf][2] = __float_as_uint(Ab[4 * MSTR]);
                apre[ks][mf][3] = __float_as_uint(Ab[4 * MSTR + 8]);
            }
        }
        if (s) { mbar_wait(fb1, pf1); pf1 ^= 1; }
        else   { mbar_wait(fb0, pf0); pf0 ^= 1; }
        const float* wb = wbuf + s * SLOTF;
#pragma unroll
        for (int ks = 0; ks < 4; ks++) {
            const float* Bb = wb + (ks * 8 + c) * WSTR + n0w + r;
#pragma unroll
            for (int nt = 0; nt < 4; nt++) {
                unsigned int b0 = __float_as_uint(Bb[nt * 8]);
                unsigned int b1 = __float_as_uint(Bb[4 * WSTR + nt * 8]);
                mma_tf32(d[0][nt], apre[ks][0][0], apre[ks][0][1],
                                   apre[ks][0][2], apre[ks][0][3], b0, b1);
                mma_tf32(d[1][nt], apre[ks][1][0], apre[ks][1][1],
                                   apre[ks][1][2], apre[ks][1][3], b0, b1);
            }
        }
        if (lane == 0) { if (s) mbar_arrive(eb1); else mbar_arrive(eb0); }
        if (tid == 0) {
            if (kb < 6) {
                if (s) { mbar_wait(eb1, pe1); pe1 ^= 1; }
                else   { mbar_wait(eb0, pe0); pe0 ^= 1; }
                unsigned int fb = s ? fb1 : fb0;
                mbar_expect_tx(fb, CTILE);
                bulk_g2s(wsm + (unsigned int)(s * SLOTB),
                         Wp + (kb + 2) * 32 * WSTR, CTILE, fb);
            } else if (nextW != nullptr) {
                if (s) {
                    mbar_wait(eb1, pe1); pe1 ^= 1;
                    mbar_expect_tx(fb1, nextBytes);
                    bulk_g2s(wsm + (unsigned int)SLOTB, nextW + nextT1Off, nextBytes, fb1);
                } else {
                    mbar_wait(eb0, pe0); pe0 ^= 1;
                    mbar_expect_tx(fb0, nextBytes);
                    bulk_g2s(wsm, nextW, nextBytes, fb0);
                }
            }
        }
    }
#pragma unroll
    for (int mf = 0; mf < 2; mf++) {
#pragma unroll
        for (int nt = 0; nt < 4; nt++) {
            const int col0 = n0w + nt * 8 + 2 * c;
            const int row = m0 + mf * 16 + r;
            float* p0 = DT + col0 * MSTR + row;
            float* p1 = DT + (col0 + 1) * MSTR + row;
            if (MODE == 1) {
                p0[0] = rna_tf32(fmaxf(d[mf][nt][0], 0.f));
                p1[0] = rna_tf32(fmaxf(d[mf][nt][1], 0.f));
                p0[8] = rna_tf32(fmaxf(d[mf][nt][2], 0.f));
                p1[8] = rna_tf32(fmaxf(d[mf][nt][3], 0.f));
            } else if (MODE == 2) {
                p0[0] = rna_tf32(p0[0] + fmaxf(d[mf][nt][0], 0.f));
                p1[0] = rna_tf32(p1[0] + fmaxf(d[mf][nt][1], 0.f));
                p0[8] = rna_tf32(p0[8] + fmaxf(d[mf][nt][2], 0.f));
                p1[8] = rna_tf32(p1[8] + fmaxf(d[mf][nt][3], 0.f));
            } else {
                p0[0] = rna_tf32(fmaxf(p0[0] + fmaxf(d[mf][nt][0], 0.f), 0.f));
                p1[0] = rna_tf32(fmaxf(p1[0] + fmaxf(d[mf][nt][1], 0.f), 0.f));
                p0[8] = rna_tf32(fmaxf(p0[8] + fmaxf(d[mf][nt][2], 0.f), 0.f));
                p1[8] = rna_tf32(fmaxf(p1[8] + fmaxf(d[mf][nt][3], 0.f), 0.f));
            }
        }
    }
}

// ---------------------------------------------------------------------------
// Rational-quadratic spline.
// ---------------------------------------------------------------------------
__device__ __forceinline__ float2 rqs_eval(const float* __restrict__ p, float xv, float splOff)
{
    float w[KBINS], hh[KBINS], d[KBINS + 1];
    float mw = p[0], mh = p[8];
#pragma unroll
    for (int j = 1; j < KBINS; j++) { mw = fmaxf(mw, p[j]); mh = fmaxf(mh, p[8 + j]); }
    float sw = 0.f, sh = 0.f;
#pragma unroll
    for (int j = 0; j < KBINS; j++) {
        w[j]  = __expf(p[j] - mw);       sw += w[j];
        hh[j] = __expf(p[8 + j] - mh);   sh += hh[j];
    }
    const float span = (RMAXF - RMINF) - KBINS * MINBIN;
    const float sclw = __fdividef(span, sw);
    const float sclh = __fdividef(span, sh);
#pragma unroll
    for (int j = 0; j < KBINS + 1; j++) {
        float v = p[16 + j] + splOff;
        d[j] = ((v > 15.f) ? v : __logf(1.f + __expf(v))) + MINSLOPE;
    }
    float xp[KBINS + 1], yp[KBINS + 1];
    xp[0] = RMINF; yp[0] = RMINF;
#pragma unroll
    for (int j = 0; j < KBINS; j++) {
        xp[j + 1] = xp[j] + fmaf(w[j], sclw, MINBIN);
        yp[j + 1] = yp[j] + fmaf(hh[j], sclh, MINBIN);
    }
    float xc = fminf(fmaxf(xv, RMINF), RMAXF);
    int idx = 0;
#pragma unroll
    for (int j = 1; j <= KBINS; j++) idx += (xc >= xp[j]) ? 1 : 0;
    idx = min(idx, KBINS - 1);
    float xk = xp[0], xk1 = xp[1], yk = yp[0], yk1 = yp[1], dk = d[0], dk1 = d[1];
#pragma unroll
    for (int j = 1; j < KBINS; j++) {
        if (idx == j) { xk = xp[j]; xk1 = xp[j + 1]; yk = yp[j]; yk1 = yp[j + 1]; dk = d[j]; dk1 = d[j + 1]; }
    }
    float bw = xk1 - xk;
    float bh = yk1 - yk;
    float s = __fdividef(bh, bw);
    float z = fminf(fmaxf(__fdividef(xc - xk, bw), 0.f), 1.f);
    float omz = 1.f - z;
    float zz = z * omz;
    float denom = fmaf(dk1 + dk - 2.f * s, zz, s);
    float y = yk + bh * __fdividef(fmaf(s * z, z, dk * zz), denom);
    float num = fmaf(dk1 * z, z, fmaf(2.f * s, zz, dk * omz * omz));
    float ld = 2.f * __logf(s) + __logf(num) - 2.f * __logf(denom);
    bool inside = (xv > RMINF) && (xv < RMAXF);
    return make_float2(inside ? y : xv, inside ? ld : 0.f);
}

// ---------------------------------------------------------------------------
extern "C" __global__ void __launch_bounds__(NTHREADS, 1)
rqs_flow_kernel(const float* __restrict__ x,
                const float* __restrict__ sc_scale,
                const float* __restrict__ sc_shift,
                const float* __restrict__ W_in,  const float* __restrict__ b_in,
                const float* __restrict__ b1b,
                const float* __restrict__ b2a,   const float* __restrict__ b2b,
                const int* __restrict__ perms,
                float* __restrict__ out)
{
    extern __shared__ __align__(16) float smem[];
    float* hT    = smem;                    // 256*MSTR
    float* rT    = hT + HDIM * MSTR;        // 256*MSTR
    float* wbuf  = rT + HDIM * MSTR;        // 2 slots x 32*WSTR
    float* xsT   = wbuf + 2 * SLOTF;        // 32*MSTR
    float* lds_s = xsT + NF * MSTR;         // 64
    float* mbm   = lds_s + MT;              // 4 mbarriers (F0,F1,E0,E1)
    float* pbuf  = smem;                    // 64 x PSTR (aliases hT/rT after sync)

    const int tid    = threadIdx.x;
    const int warpid = tid >> 5;
    const int lane   = tid & 31;
    const long long base = (long long)blockIdx.x * MT;
    const unsigned int wsm = (unsigned int)__cvta_generic_to_shared(wbuf);
    const unsigned int fb0 = (unsigned int)__cvta_generic_to_shared(mbm);
    const unsigned int fb1 = fb0 + 8;
    const unsigned int eb0 = fb0 + 16;
    const unsigned int eb1 = fb0 + 24;
    int pf0 = 0, pf1 = 0, pe0 = 0, pe1 = 0;

    // load x transposed: xsT[n][m]
    {
        const int m  = tid >> 3;
        const int n4 = (tid & 7) << 2;
        float4 gx = *reinterpret_cast<const float4*>(x + (base + m) * NF + n4);
        xsT[(n4 + 0) * MSTR + m] = gx.x;
        xsT[(n4 + 1) * MSTR + m] = gx.y;
        xsT[(n4 + 2) * MSTR + m] = gx.z;
        xsT[(n4 + 3) * MSTR + m] = gx.w;
    }
    if (tid < MT) lds_s[tid] = 0.f;
    if (tid == 0) {
        mbar_init(fb0, 1); mbar_init(fb1, 1);
        mbar_init(eb0, 16); mbar_init(eb1, 16);
    }
    const float splOff = logf(expm1f(1.0f - MINSLOPE));
    __syncthreads();

    // prologue: prefetch layer 0's W1b 32-row tiles 0/1 into slots 0/1
    if (tid == 0) {
        const float* W1b0 = g_wpad + 1 * HDIM * WSTR;
        mbar_expect_tx(fb0, CTILE);
        bulk_g2s(wsm, W1b0, CTILE, fb0);
        mbar_expect_tx(fb1, CTILE);
        bulk_g2s(wsm + (unsigned int)SLOTB, W1b0 + 32 * WSTR, CTILE, fb1);
    }

    for (int i = 0; i < LL; i++) {
        const int koff = (i & 1) ? 0 : 1;   // conditioner-input parity
        const int toff = 1 - koff;          // transformed parity (= i&1)

        // ---- permute + affine ----
        {
            const int*   pm  = perms    + i * NF;
            const float* scs = sc_scale + i * NF;
            const float* sch = sc_shift + i * NF;
            const int n  = tid >> 4;
            const int ms = (tid & 15) << 2;
            const float s  = scs[n];
            const float sh = sch[n];
            const int   pn = pm[n];
            float tmp[4];
#pragma unroll
            for (int q = 0; q < 4; q++)
                tmp[q] = fmaf(xsT[pn * MSTR + ms + q], s, sh);
            __syncthreads();
#pragma unroll
            for (int q = 0; q < 4; q++)
                xsT[n * MSTR + ms + q] = tmp[q];
            __syncthreads();
        }

        // ---- conditioner: hT = h (raw fp32), rT = rna(relu(mx@Wf + bf)) ----
        const float* Wp = g_wpad + (size_t)i * 4 * HDIM * WSTR;
        mmIn<0, 2>(W_in + i * NF * HDIM, b_in + i * HDIM, xsT, hT, warpid, lane, koff);
        mmIn<1, 1>(g_wf + i * 16 * HDIM, g_bf + i * HDIM, xsT, rT, warpid, lane, koff);
        __syncthreads();

        // W1b: hT = rna(h + relu(rT @ W1b + b1b))   [W1a folded into rT]
        mm256t<2>(Wp + 1 * HDIM * WSTR, b1b + i * HDIM, rT, hT, wbuf, wsm,
                  Wp + 2 * HDIM * WSTR, CTILE, 32 * WSTR,
                  fb0, fb1, eb0, eb1, pf0, pf1, pe0, pe1, warpid, lane, tid);
        __syncthreads();
        mm256t<1>(Wp + 2 * HDIM * WSTR, b2a + i * HDIM, hT, rT, wbuf, wsm,
                  Wp + 3 * HDIM * WSTR, CTILE, 32 * WSTR,
                  fb0, fb1, eb0, eb1, pf0, pf1, pe0, pe1, warpid, lane, tid);
        __syncthreads();
        mm256t<3>(Wp + 3 * HDIM * WSTR, b2b + i * HDIM, rT, hT, wbuf, wsm,
                  g_wopad + (size_t)i * HDIM * WOSTR, WOTILE, 16 * WOSTR,
                  fb0, fb1, eb0, eb1, pf0, pf1, pe0, pe1, warpid, lane, tid);
        __syncthreads();   // hT = relu(h3), A operand for W_out mma

        // ---- W_out tf32 mma (16-row tiles, tiles 0/1 prefetched by W2b), m16n104 ----
        {
            const float* Wop = g_wopad + (size_t)i * HDIM * WOSTR;
            const float* bop = g_bopad + i * 416;
            const float* nextW1b = (i < LL - 1)
                ? g_wpad + (size_t)(i + 1) * 4 * HDIM * WSTR + HDIM * WSTR : nullptr;
            const int mwp = warpid & 3, nw = warpid >> 2;
            const int m0f = mwp << 4;
            const int n0w = nw * 104;
            const int r = lane >> 2, c = lane & 3;

            float d[13][4];
#pragma unroll
            for (int nt = 0; nt < 13; nt++) {
                int col0 = n0w + nt * 8 + 2 * c;
                float b0 = bop[col0], b1 = bop[col0 + 1];
                d[nt][0] = b0; d[nt][1] = b1; d[nt][2] = b0; d[nt][3] = b1;
            }

#pragma unroll 1
            for (int kb = 0; kb < 16; kb++) {
                const int s = kb & 1;
                // preload BOTH ks A fragments before the wait
                unsigned int apre[2][4];
#pragma unroll
                for (int ks = 0; ks < 2; ks++) {
                    const float* Ab = hT + (kb * 16 + ks * 8 + c) * MSTR + m0f + r;
                    apre[ks][0] = __float_as_uint(Ab[0]);
                    apre[ks][1] = __float_as_uint(Ab[8]);
                    apre[ks][2] = __float_as_uint(Ab[4 * MSTR]);
                    apre[ks][3] = __float_as_uint(Ab[4 * MSTR + 8]);
                }
                if (s) { mbar_wait(fb1, pf1); pf1 ^= 1; }
                else   { mbar_wait(fb0, pf0); pf0 ^= 1; }
                const float* wb = wbuf + s * SLOTF;
#pragma unroll
                for (int ks = 0; ks < 2; ks++) {
                    const float* Bb = wb + (ks * 8 + c) * WOSTR + n0w + r;
#pragma unroll
                    for (int nt = 0; nt < 13; nt++) {
                        unsigned int b0 = __float_as_uint(Bb[nt * 8]);
                        unsigned int b1 = __float_as_uint(Bb[4 * WOSTR + nt * 8]);
                        mma_tf32(d[nt], apre[ks][0], apre[ks][1],
                                        apre[ks][2], apre[ks][3], b0, b1);
                    }
                }
                if (lane == 0) { if (s) mbar_arrive(eb1); else mbar_arrive(eb0); }
                if (tid == 0) {
                    if (kb < 14) {
                        if (s) { mbar_wait(eb1, pe1); pe1 ^= 1; }
                        else   { mbar_wait(eb0, pe0); pe0 ^= 1; }
                        unsigned int fb = s ? fb1 : fb0;
                        mbar_expect_tx(fb, WOTILE);
                        bulk_g2s(wsm + (unsigned int)(s * SLOTB),
                                 Wop + (kb + 2) * 16 * WOSTR, WOTILE, fb);
                    } else if (nextW1b != nullptr) {
                        if (s) {
                            mbar_wait(eb1, pe1); pe1 ^= 1;
                            mbar_expect_tx(fb1, CTILE);
                            bulk_g2s(wsm + (unsigned int)SLOTB,
                                     nextW1b + 32 * WSTR, CTILE, fb1);
                        } else {
                            mbar_wait(eb0, pe0); pe0 ^= 1;
                            mbar_expect_tx(fb0, CTILE);
                            bulk_g2s(wsm, nextW1b, CTILE, fb0);
                        }
                    }
                }
            }
            __syncthreads();   // all warps done reading hT before pbuf overwrites it

#pragma unroll
            for (int nt = 0; nt < 13; nt++) {
                const int col0 = n0w + nt * 8 + 2 * c;
                if (col0 < 400) {
                    pbuf[(m0f + r) * PSTR + col0]         = d[nt][0];
                    pbuf[(m0f + r) * PSTR + col0 + 1]     = d[nt][1];
                    pbuf[(m0f + r + 8) * PSTR + col0]     = d[nt][2];
                    pbuf[(m0f + r + 8) * PSTR + col0 + 1] = d[nt][3];
                }
            }
            __syncthreads();

            // ---- spline: warp = packed dim j (actual n = 2j+toff), lane -> 2 rows ----
            const int n  = 2 * warpid + toff;
            const int m0 = lane << 1;
            float ldv[2];
#pragma unroll
            for (int mi = 0; mi < 2; mi++) {
                float pr[PP];
                const float* psrc = pbuf + (m0 + mi) * PSTR + warpid * PP;
#pragma unroll
                for (int p = 0; p < PP; p++) pr[p] = psrc[p];
                float xv = xsT[n * MSTR + m0 + mi];
                float2 rr = rqs_eval(pr, xv, splOff);
                xsT[n * MSTR + m0 + mi] = rr.x;
                ldv[mi] = rr.y;
            }
            atomicAdd(&lds_s[m0],     ldv[0]);
            atomicAdd(&lds_s[m0 + 1], ldv[1]);
        }
        __syncthreads();
    }

    // ---- final log-prob ----
    if (tid < MT) {
        const int m = tid;
        float s2 = 0.f;
#pragma unroll
        for (int nn = 0; nn < NF; nn++) {
            float v = xsT[nn * MSTR + m];
            s2 = fmaf(v, v, s2);
        }
        float C = 0.f;
        for (int i = 0; i < LL; i++)
            for (int nn = 0; nn < NF; nn++)
                C += __logf(fabsf(sc_scale[i * NF + nn]));
        out[base + m] = -0.5f * s2 - 0.5f * (float)NF * 1.8378770664093453f + lds_s[m] + C;
    }
}

// ---------------------------------------------------------------------------
extern "C" void kernel_launch(void* const* d_in, const int* in_sizes, int n_in,
                              void* d_out, int out_size)
{
    const float* x        = (const float*)d_in[0];
    const float* sc_scale = (const float*)d_in[1];
    const float* sc_shift = (const float*)d_in[2];
    const float* W_in     = (const float*)d_in[3];
    const float* b_in     = (const float*)d_in[4];
    const float* W1a      = (const float*)d_in[5];
    const float* b1a      = (const float*)d_in[6];
    const float* W1b      = (const float*)d_in[7];
    const float* b1b      = (const float*)d_in[8];
    const float* W2a      = (const float*)d_in[9];
    const float* b2a      = (const float*)d_in[10];
    const float* W2b      = (const float*)d_in[11];
    const float* b2b      = (const float*)d_in[12];
    const float* W_out    = (const float*)d_in[13];
    const float* b_out    = (const float*)d_in[14];
    const int*   perms    = (const int*)d_in[15];

    // prep: pad/convert weights + fold W1a into the low-rank input path
    {
        const long long totalA = (long long)LL * 4 * HDIM * WSTR;
        prep_weights<<<(int)((totalA + 255) / 256), 256>>>(W1a, W1b, W2a, W2b);
        const long long totalO = (long long)LL * HDIM * WOSTR;
        prep_wout<<<(int)((totalO + 255) / 256), 256>>>(W_out, b_out);
        const int totalF = LL * 16 * HDIM;
        prep_fused<<<(totalF + 255) / 256, 256>>>(W_in, b_in, W1a, b1a);
    }

    const int B = in_sizes[0] / NF;
    const int grid = B / MT;
    const size_t smem = (size_t)(2 * HDIM * MSTR + 2 * SLOTF + NF * MSTR + MT + 8)
                        * sizeof(float);

    cudaFuncSetAttribute(rqs_flow_kernel,
                         cudaFuncAttributeMaxDynamicSharedMemorySize, (int)smem);

    rqs_flow_kernel<<<grid, NTHREADS, smem>>>(
        x, sc_scale, sc_shift, W_in, b_in, b1b, b2a, b2b,
        perms, (float*)d_out);
}

// round 16
// speedup vs baseline: 1.0236x; 1.0236x over previous
#include <cuda_runtime.h>
#include <cstdint>

#define NF 32
#define LL 8
#define HDIM 256
#define KBINS 8
#define PP 25
#define NP 800
#define MT 64
#define NTHREADS 512
#define MSTR 72         // activation stride [k][m]: mod 32 = 8 -> conflict-free mma frags
#define WSTR 264        // padded tf32 conditioner-weight row stride (mod 32 = 8)
#define WOSTR 424       // padded tf32 W_out row stride (mod 32 = 8), 416 cols used
#define PSTR 401        // params buffer stride

#define RMINF (-10.0f)
#define RMAXF (10.0f)
#define MINBIN (1e-4f)
#define MINSLOPE (1e-4f)

#define CTILE  ((unsigned int)(32 * WSTR * 4))    // 33792 B (conditioner 32-row tile)
#define WOTILE ((unsigned int)(16 * WOSTR * 4))   // 27136 B (W_out 16-row tile)
#define SLOTB  CTILE                               // slot byte stride (max payload)
#define SLOTF  (32 * WSTR)                         // slot stride in floats

typedef unsigned long long u64;

__device__ __align__(16) float g_wpad[(size_t)LL * 4 * HDIM * WSTR];
__device__ __align__(16) float g_wopad[(size_t)LL * HDIM * WOSTR];
__device__ __align__(16) float g_bopad[LL * 416];
__device__ __align__(16) float g_wf[LL * 16 * HDIM];   // fp32 fused W_in@W1a
__device__ __align__(16) float g_bf[LL * HDIM];        // fp32 fused b_in@W1a + b1a

__device__ __forceinline__ u64 pack2(float lo, float hi) {
    u64 r; asm("mov.b64 %0, {%1,%2};" : "=l"(r) : "f"(lo), "f"(hi)); return r;
}
__device__ __forceinline__ float2 unpack2(u64 v) {
    float2 r; asm("mov.b64 {%0,%1}, %2;" : "=f"(r.x), "=f"(r.y) : "l"(v)); return r;
}
__device__ __forceinline__ void fma2(u64& d, u64 a, u64 b) {
    asm("fma.rn.f32x2 %0, %1, %2, %0;" : "+l"(d) : "l"(a), "l"(b));
}
__device__ __forceinline__ float rna_tf32(float v) {
    unsigned int u; asm("cvt.rna.tf32.f32 %0, %1;" : "=r"(u) : "f"(v));
    return __uint_as_float(u);
}
__device__ __forceinline__ void mma_tf32(float* d,
                                         unsigned int a0, unsigned int a1,
                                         unsigned int a2, unsigned int a3,
                                         unsigned int b0, unsigned int b1) {
    asm("mma.sync.aligned.m16n8k8.row.col.f32.tf32.tf32.f32 "
        "{%0,%1,%2,%3}, {%4,%5,%6,%7}, {%8,%9}, {%0,%1,%2,%3};"
        : "+f"(d[0]), "+f"(d[1]), "+f"(d[2]), "+f"(d[3])
        : "r"(a0), "r"(a1), "r"(a2), "r"(a3), "r"(b0), "r"(b1));
}

// ---- mbarrier + 1D bulk-async helpers ----
__device__ __forceinline__ void mbar_init(unsigned int mbar, unsigned int cnt) {
    asm volatile("mbarrier.init.shared.b64 [%0], %1;" :: "r"(mbar), "r"(cnt) : "memory");
}
__device__ __forceinline__ void mbar_expect_tx(unsigned int mbar, unsigned int bytes) {
    asm volatile("mbarrier.arrive.expect_tx.shared.b64 _, [%0], %1;"
                 :: "r"(mbar), "r"(bytes) : "memory");
}
__device__ __forceinline__ void mbar_arrive(unsigned int mbar) {
    asm volatile("mbarrier.arrive.shared.b64 _, [%0];" :: "r"(mbar) : "memory");
}
__device__ __forceinline__ void bulk_g2s(unsigned int dst, const void* src,
                                         unsigned int bytes, unsigned int mbar) {
    asm volatile("cp.async.bulk.shared::cluster.global.mbarrier::complete_tx::bytes "
                 "[%0], [%1], %2, [%3];"
                 :: "r"(dst), "l"(src), "r"(bytes), "r"(mbar) : "memory");
}
__device__ __forceinline__ void mbar_wait(unsigned int mbar, int parity) {
    unsigned int done;
    asm volatile(
        "{\n\t.reg .pred p;\n\t"
        "mbarrier.try_wait.parity.acquire.cta.shared::cta.b64 p, [%1], %2;\n\t"
        "selp.b32 %0, 1, 0, p;\n\t}"
        : "=r"(done) : "r"(mbar), "r"(parity) : "memory");
    if (!done) {
        asm volatile(
            "{\n\t.reg .pred P1;\n\t"
            "WAIT_LOOP_%=:\n\t"
            "mbarrier.try_wait.parity.acquire.cta.shared::cta.b64 P1, [%0], %1, 0x989680;\n\t"
            "@P1 bra.uni WAIT_DONE_%=;\n\t"
            "bra.uni WAIT_LOOP_%=;\n\t"
            "WAIT_DONE_%=:\n\t}"
            :: "r"(mbar), "r"(parity) : "memory");
    }
}
// Relaxed wait: producer-only (post-wait accesses are async-proxy bulk copies).
__device__ __forceinline__ void mbar_wait_relaxed(unsigned int mbar, int parity) {
    unsigned int done;
    asm volatile(
        "{\n\t.reg .pred p;\n\t"
        "mbarrier.try_wait.parity.relaxed.cta.shared::cta.b64 p, [%1], %2;\n\t"
        "selp.b32 %0, 1, 0, p;\n\t}"
        : "=r"(done) : "r"(mbar), "r"(parity) : "memory");
    if (!done) {
        asm volatile(
            "{\n\t.reg .pred P1;\n\t"
            "WAIT_LOOP_%=:\n\t"
            "mbarrier.try_wait.parity.relaxed.cta.shared::cta.b64 P1, [%0], %1, 0x989680;\n\t"
            "@P1 bra.uni WAIT_DONE_%=;\n\t"
            "bra.uni WAIT_LOOP_%=;\n\t"
            "WAIT_DONE_%=:\n\t}"
            :: "r"(mbar), "r"(parity) : "memory");
    }
}

// ---------------------------------------------------------------------------
// Prep kernels
// ---------------------------------------------------------------------------
extern "C" __global__ void prep_weights(const float* __restrict__ W1a,
                                        const float* __restrict__ W1b,
                                        const float* __restrict__ W2a,
                                        const float* __restrict__ W2b)
{
    long long idx = (long long)blockIdx.x * blockDim.x + threadIdx.x;
    const long long total = (long long)LL * 4 * HDIM * WSTR;
    if (idx >= total) return;
    int col = (int)(idx % WSTR);
    long long t = idx / WSTR;
    int row = (int)(t % HDIM);
    int mat = (int)(t / HDIM);
    int i = mat >> 2, j = mat & 3;
    const float* src = (j == 0 ? W1a : j == 1 ? W1b : j == 2 ? W2a : W2b);
    float v = (col < HDIM) ? src[(long long)i * HDIM * HDIM + row * HDIM + col] : 0.f;
    g_wpad[idx] = rna_tf32(v);
}

// Pack W_out: layer i, dim j (actual n=2j+(i&1)) occupies cols [25j, 25j+25), pad to 416.
extern "C" __global__ void prep_wout(const float* __restrict__ Wo,
                                     const float* __restrict__ bo)
{
    long long idx = (long long)blockIdx.x * blockDim.x + threadIdx.x;
    const long long totalW = (long long)LL * HDIM * WOSTR;
    if (idx < totalW) {
        int col = (int)(idx % WOSTR);
        long long t = idx / WOSTR;
        int row = (int)(t % HDIM);
        int i = (int)(t / HDIM);
        int toff = i & 1;
        float v = 0.f;
        if (col < 400) {
            int j = col / 25, p = col - j * 25;
            v = Wo[(long long)i * HDIM * NP + (long long)row * NP + (2 * j + toff) * PP + p];
        }
        g_wopad[idx] = rna_tf32(v);
    }
    if (idx < LL * 416) {
        int i = (int)(idx / 416), col = (int)(idx % 416);
        int toff = i & 1;
        float v = 0.f;
        if (col < 400) {
            int j = col / 25, p = col - j * 25;
            v = bo[i * NP + (2 * j + toff) * PP + p];
        }
        g_bopad[idx] = v;
    }
}

extern "C" __global__ void prep_fused(const float* __restrict__ W_in,
                                      const float* __restrict__ b_in,
                                      const float* __restrict__ W1a,
                                      const float* __restrict__ b1a)
{
    int idx = blockIdx.x * blockDim.x + threadIdx.x;
    const int totalW = LL * 16 * HDIM;
    if (idx < totalW) {
        int c = idx % HDIM;
        int t = idx / HDIM;
        int k = t % 16;
        int i = t / 16;
        int koff = (i & 1) ? 0 : 1;
        int n = 2 * k + koff;
        const float* wi = W_in + ((size_t)i * NF + n) * HDIM;
        const float* wa = W1a + (size_t)i * HDIM * HDIM + c;
        float s = 0.f;
        for (int j = 0; j < HDIM; j++) s = fmaf(wi[j], wa[(size_t)j * HDIM], s);
        g_wf[idx] = s;
    }
    if (idx < LL * HDIM) {
        int c = idx % HDIM;
        int i = idx / HDIM;
        const float* bi = b_in + i * HDIM;
        const float* wa = W1a + (size_t)i * HDIM * HDIM + c;
        float s = b1a[i * HDIM + c];
        for (int j = 0; j < HDIM; j++) s = fmaf(bi[j], wa[(size_t)j * HDIM], s);
        g_bf[idx] = s;
    }
}

// ---------------------------------------------------------------------------
// mmIn (16 warps): warp -> 16 cols, lane -> 2 rows.
// ---------------------------------------------------------------------------
template <int STORE, int RSTRIDE>
__device__ __forceinline__ void mmIn(const float* __restrict__ W,
                                     const float* __restrict__ bi,
                                     const float* __restrict__ xsT,
                                     float* __restrict__ DT,
                                     int warpid, int lane, int rowOff)
{
    const int cb = warpid << 4;
    const int m0 = lane << 1;
    u64 acc[2][8];
    const ulonglong2* bp = reinterpret_cast<const ulonglong2*>(bi + cb);
#pragma unroll
    for (int q = 0; q < 4; q++) {
        ulonglong2 b = bp[q];
        acc[0][2*q] = b.x; acc[0][2*q+1] = b.y;
        acc[1][2*q] = b.x; acc[1][2*q+1] = b.y;
    }
#pragma unroll
    for (int k = 0; k < 16; k++) {
        const int n = 2*k + rowOff;
        const int wr = (RSTRIDE == 2) ? n : k;
        float2 av = *reinterpret_cast<const float2*>(xsT + n*MSTR + m0);
        u64 a0 = pack2(av.x, av.x);
        u64 a1 = pack2(av.y, av.y);
        const ulonglong2* wp = reinterpret_cast<const ulonglong2*>(W + wr*HDIM + cb);
#pragma unroll
        for (int q = 0; q < 4; q++) {
            ulonglong2 w = wp[q];
            fma2(acc[0][2*q],   a0, w.x);
            fma2(acc[0][2*q+1], a0, w.y);
            fma2(acc[1][2*q],   a1, w.x);
            fma2(acc[1][2*q+1], a1, w.y);
        }
    }
#pragma unroll
    for (int q = 0; q < 8; q++) {
        float2 r0 = unpack2(acc[0][q]);
        float2 r1 = unpack2(acc[1][q]);
        float v00 = r0.x, v10 = r1.x, v01 = r0.y, v11 = r1.y;
        if (STORE == 1) {
            v00 = rna_tf32(fmaxf(v00, 0.f)); v10 = rna_tf32(fmaxf(v10, 0.f));
            v01 = rna_tf32(fmaxf(v01, 0.f)); v11 = rna_tf32(fmaxf(v11, 0.f));
        }
        *reinterpret_cast<float2*>(DT + (cb + 2*q)*MSTR + m0)     = make_float2(v00, v10);
        *reinterpret_cast<float2*>(DT + (cb + 2*q + 1)*MSTR + m0) = make_float2(v01, v11);
    }
}

// ---------------------------------------------------------------------------
// mm256 tf32 mma, m32n32 warp tiles (2m x 8n). 32-row k-tiles (8 rendezvous).
// ks=0 A fragments preloaded BEFORE the full-barrier wait (AT is stable).
// MODE 1: D=rna(relu); 2: D=rna(D+relu); 3: D=rna(relu(D+relu)).
// ---------------------------------------------------------------------------
template <int MODE>
__device__ __forceinline__ void mm256t(const float* __restrict__ Wp,
                                       const float* __restrict__ bias,
                                       const float* __restrict__ AT,
                                       float* __restrict__ DT,
                                       const float* __restrict__ wbuf, unsigned int wsm,
                                       const float* __restrict__ nextW,
                                       unsigned int nextBytes, int nextT1Off,
                                       unsigned int fb0, unsigned int fb1,
                                       unsigned int eb0, unsigned int eb1,
                                       int& pf0, int& pf1, int& pe0, int& pe1,
                                       int warpid, int lane, int tid)
{
    const int mwp = warpid & 1, nw = warpid >> 1;
    const int m0 = mwp << 5;
    const int n0w = nw << 5;
    const int r = lane >> 2, c = lane & 3;

    float d[2][4][4];
#pragma unroll
    for (int nt = 0; nt < 4; nt++) {
        float b0 = bias[n0w + nt*8 + 2*c];
        float b1 = bias[n0w + nt*8 + 2*c + 1];
#pragma unroll
        for (int mf = 0; mf < 2; mf++) {
            d[mf][nt][0] = b0; d[mf][nt][1] = b1;
            d[mf][nt][2] = b0; d[mf][nt][3] = b1;
        }
    }

#pragma unroll 1
    for (int kb = 0; kb < 8; kb++) {
        const int s = kb & 1;
        // preload ks=0 A fragments before the wait
        unsigned int apre[2][4];
        {
            const int k0 = kb * 32;
#pragma unroll
            for (int mf = 0; mf < 2; mf++) {
                const float* Ab = AT + (k0 + c) * MSTR + m0 + mf * 16 + r;
                apre[mf][0] = __float_as_uint(Ab[0]);
                apre[mf][1] = __float_as_uint(Ab[8]);
                apre[mf][2] = __float_as_uint(Ab[4 * MSTR]);
                apre[mf][3] = __float_as_uint(Ab[4 * MSTR + 8]);
            }
        }
        if (s) { mbar_wait(fb1, pf1); pf1 ^= 1; }
        else   { mbar_wait(fb0, pf0); pf0 ^= 1; }
        const float* wb = wbuf + s * SLOTF;
#pragma unroll
        for (int ks = 0; ks < 4; ks++) {
            const int k0 = kb * 32 + ks * 8;
            unsigned int a[2][4];
            if (ks == 0) {
#pragma unroll
                for (int mf = 0; mf < 2; mf++)
#pragma unroll
                    for (int q = 0; q < 4; q++) a[mf][q] = apre[mf][q];
            } else {
#pragma unroll
                for (int mf = 0; mf < 2; mf++) {
                    const float* Ab = AT + (k0 + c) * MSTR + m0 + mf * 16 + r;
                    a[mf][0] = __float_as_uint(Ab[0]);
                    a[mf][1] = __float_as_uint(Ab[8]);
                    a[mf][2] = __float_as_uint(Ab[4 * MSTR]);
                    a[mf][3] = __float_as_uint(Ab[4 * MSTR + 8]);
                }
            }
            const float* Bb = wb + (ks * 8 + c) * WSTR + n0w + r;
#pragma unroll
            for (int nt = 0; nt < 4; nt++) {
                unsigned int b0 = __float_as_uint(Bb[nt * 8]);
                unsigned int b1 = __float_as_uint(Bb[4 * WSTR + nt * 8]);
                mma_tf32(d[0][nt], a[0][0], a[0][1], a[0][2], a[0][3], b0, b1);
                mma_tf32(d[1][nt], a[1][0], a[1][1], a[1][2], a[1][3], b0, b1);
            }
        }
        if (lane == 0) { if (s) mbar_arrive(eb1); else mbar_arrive(eb0); }
        if (tid == 0) {
            if (kb < 6) {
                if (s) { mbar_wait_relaxed(eb1, pe1); pe1 ^= 1; }
                else   { mbar_wait_relaxed(eb0, pe0); pe0 ^= 1; }
                unsigned int fb = s ? fb1 : fb0;
                mbar_expect_tx(fb, CTILE);
                bulk_g2s(wsm + (unsigned int)(s * SLOTB),
                         Wp + (kb + 2) * 32 * WSTR, CTILE, fb);
            } else if (nextW != nullptr) {
                if (s) {
                    mbar_wait_relaxed(eb1, pe1); pe1 ^= 1;
                    mbar_expect_tx(fb1, nextBytes);
                    bulk_g2s(wsm + (unsigned int)SLOTB, nextW + nextT1Off, nextBytes, fb1);
                } else {
                    mbar_wait_relaxed(eb0, pe0); pe0 ^= 1;
                    mbar_expect_tx(fb0, nextBytes);
                    bulk_g2s(wsm, nextW, nextBytes, fb0);
                }
            }
        }
    }
#pragma unroll
    for (int mf = 0; mf < 2; mf++) {
#pragma unroll
        for (int nt = 0; nt < 4; nt++) {
            const int col0 = n0w + nt * 8 + 2 * c;
            const int row = m0 + mf * 16 + r;
            float* p0 = DT + col0 * MSTR + row;
            float* p1 = DT + (col0 + 1) * MSTR + row;
            if (MODE == 1) {
                p0[0] = rna_tf32(fmaxf(d[mf][nt][0], 0.f));
                p1[0] = rna_tf32(fmaxf(d[mf][nt][1], 0.f));
                p0[8] = rna_tf32(fmaxf(d[mf][nt][2], 0.f));
                p1[8] = rna_tf32(fmaxf(d[mf][nt][3], 0.f));
            } else if (MODE == 2) {
                p0[0] = rna_tf32(p0[0] + fmaxf(d[mf][nt][0], 0.f));
                p1[0] = rna_tf32(p1[0] + fmaxf(d[mf][nt][1], 0.f));
                p0[8] = rna_tf32(p0[8] + fmaxf(d[mf][nt][2], 0.f));
                p1[8] = rna_tf32(p1[8] + fmaxf(d[mf][nt][3], 0.f));
            } else {
                p0[0] = rna_tf32(fmaxf(p0[0] + fmaxf(d[mf][nt][0], 0.f), 0.f));
                p1[0] = rna_tf32(fmaxf(p1[0] + fmaxf(d[mf][nt][1], 0.f), 0.f));
                p0[8] = rna_tf32(fmaxf(p0[8] + fmaxf(d[mf][nt][2], 0.f), 0.f));
                p1[8] = rna_tf32(fmaxf(p1[8] + fmaxf(d[mf][nt][3], 0.f), 0.f));
            }
        }
    }
}

// ---------------------------------------------------------------------------
// Rational-quadratic spline.
// ---------------------------------------------------------------------------
__device__ __forceinline__ float2 rqs_eval(const float* __restrict__ p, float xv, float splOff)
{
    float w[KBINS], hh[KBINS], d[KBINS + 1];
    float mw = p[0], mh = p[8];
#pragma unroll
    for (int j = 1; j < KBINS; j++) { mw = fmaxf(mw, p[j]); mh = fmaxf(mh, p[8 + j]); }
    float sw = 0.f, sh = 0.f;
#pragma unroll
    for (int j = 0; j < KBINS; j++) {
        w[j]  = __expf(p[j] - mw);       sw += w[j];
        hh[j] = __expf(p[8 + j] - mh);   sh += hh[j];
    }
    const float span = (RMAXF - RMINF) - KBINS * MINBIN;
    const float sclw = __fdividef(span, sw);
    const float sclh = __fdividef(span, sh);
#pragma unroll
    for (int j = 0; j < KBINS + 1; j++) {
        float v = p[16 + j] + splOff;
        d[j] = ((v > 15.f) ? v : __logf(1.f + __expf(v))) + MINSLOPE;
    }
    float xp[KBINS + 1], yp[KBINS + 1];
    xp[0] = RMINF; yp[0] = RMINF;
#pragma unroll
    for (int j = 0; j < KBINS; j++) {
        xp[j + 1] = xp[j] + fmaf(w[j], sclw, MINBIN);
        yp[j + 1] = yp[j] + fmaf(hh[j], sclh, MINBIN);
    }
    float xc = fminf(fmaxf(xv, RMINF), RMAXF);
    int idx = 0;
#pragma unroll
    for (int j = 1; j <= KBINS; j++) idx += (xc >= xp[j]) ? 1 : 0;
    idx = min(idx, KBINS - 1);
    float xk = xp[0], xk1 = xp[1], yk = yp[0], yk1 = yp[1], dk = d[0], dk1 = d[1];
#pragma unroll
    for (int j = 1; j < KBINS; j++) {
        if (idx == j) { xk = xp[j]; xk1 = xp[j + 1]; yk = yp[j]; yk1 = yp[j + 1]; dk = d[j]; dk1 = d[j + 1]; }
    }
    float bw = xk1 - xk;
    float bh = yk1 - yk;
    float s = __fdividef(bh, bw);
    float z = fminf(fmaxf(__fdividef(xc - xk, bw), 0.f), 1.f);
    float omz = 1.f - z;
    float zz = z * omz;
    float denom = fmaf(dk1 + dk - 2.f * s, zz, s);
    float y = yk + bh * __fdividef(fmaf(s * z, z, dk * zz), denom);
    float num = fmaf(dk1 * z, z, fmaf(2.f * s, zz, dk * omz * omz));
    float ld = 2.f * __logf(s) + __logf(num) - 2.f * __logf(denom);
    bool inside = (xv > RMINF) && (xv < RMAXF);
    return make_float2(inside ? y : xv, inside ? ld : 0.f);
}

// ---------------------------------------------------------------------------
extern "C" __global__ void __launch_bounds__(NTHREADS, 1)
rqs_flow_kernel(const float* __restrict__ x,
                const float* __restrict__ sc_scale,
                const float* __restrict__ sc_shift,
                const float* __restrict__ W_in,  const float* __restrict__ b_in,
                const float* __restrict__ b1b,
                const float* __restrict__ b2a,   const float* __restrict__ b2b,
                const int* __restrict__ perms,
                float* __restrict__ out)
{
    extern __shared__ __align__(16) float smem[];
    float* hT    = smem;                    // 256*MSTR
    float* rT    = hT + HDIM * MSTR;        // 256*MSTR
    float* wbuf  = rT + HDIM * MSTR;        // 2 slots x 32*WSTR
    float* xsT   = wbuf + 2 * SLOTF;        // 32*MSTR
    float* lds_s = xsT + NF * MSTR;         // 64
    float* mbm   = lds_s + MT;              // 4 mbarriers (F0,F1,E0,E1)
    float* pbuf  = smem;                    // 64 x PSTR (aliases hT/rT after sync)

    const int tid    = threadIdx.x;
    const int warpid = tid >> 5;
    const int lane   = tid & 31;
    const long long base = (long long)blockIdx.x * MT;
    const unsigned int wsm = (unsigned int)__cvta_generic_to_shared(wbuf);
    const unsigned int fb0 = (unsigned int)__cvta_generic_to_shared(mbm);
    const unsigned int fb1 = fb0 + 8;
    const unsigned int eb0 = fb0 + 16;
    const unsigned int eb1 = fb0 + 24;
    int pf0 = 0, pf1 = 0, pe0 = 0, pe1 = 0;

    // load x transposed: xsT[n][m]
    {
        const int m  = tid >> 3;
        const int n4 = (tid & 7) << 2;
        float4 gx = *reinterpret_cast<const float4*>(x + (base + m) * NF + n4);
        xsT[(n4 + 0) * MSTR + m] = gx.x;
        xsT[(n4 + 1) * MSTR + m] = gx.y;
        xsT[(n4 + 2) * MSTR + m] = gx.z;
        xsT[(n4 + 3) * MSTR + m] = gx.w;
    }
    if (tid < MT) lds_s[tid] = 0.f;
    if (tid == 0) {
        mbar_init(fb0, 1); mbar_init(fb1, 1);
        mbar_init(eb0, 16); mbar_init(eb1, 16);
    }
    const float splOff = logf(expm1f(1.0f - MINSLOPE));
    __syncthreads();

    // prologue: prefetch layer 0's W1b 32-row tiles 0/1 into slots 0/1
    if (tid == 0) {
        const float* W1b0 = g_wpad + 1 * HDIM * WSTR;
        mbar_expect_tx(fb0, CTILE);
        bulk_g2s(wsm, W1b0, CTILE, fb0);
        mbar_expect_tx(fb1, CTILE);
        bulk_g2s(wsm + (unsigned int)SLOTB, W1b0 + 32 * WSTR, CTILE, fb1);
    }

    for (int i = 0; i < LL; i++) {
        const int koff = (i & 1) ? 0 : 1;   // conditioner-input parity
        const int toff = 1 - koff;          // transformed parity (= i&1)

        // ---- permute + affine ----
        {
            const int*   pm  = perms    + i * NF;
            const float* scs = sc_scale + i * NF;
            const float* sch = sc_shift + i * NF;
            const int n  = tid >> 4;
            const int ms = (tid & 15) << 2;
            const float s  = scs[n];
            const float sh = sch[n];
            const int   pn = pm[n];
            float tmp[4];
#pragma unroll
            for (int q = 0; q < 4; q++)
                tmp[q] = fmaf(xsT[pn * MSTR + ms + q], s, sh);
            __syncthreads();
#pragma unroll
            for (int q = 0; q < 4; q++)
                xsT[n * MSTR + ms + q] = tmp[q];
            __syncthreads();
        }

        // ---- conditioner: hT = h (raw fp32), rT = rna(relu(mx@Wf + bf)) ----
        const float* Wp = g_wpad + (size_t)i * 4 * HDIM * WSTR;
        mmIn<0, 2>(W_in + i * NF * HDIM, b_in + i * HDIM, xsT, hT, warpid, lane, koff);
        mmIn<1, 1>(g_wf + i * 16 * HDIM, g_bf + i * HDIM, xsT, rT, warpid, lane, koff);
        __syncthreads();

        // W1b: hT = rna(h + relu(rT @ W1b + b1b))   [W1a folded into rT]
        mm256t<2>(Wp + 1 * HDIM * WSTR, b1b + i * HDIM, rT, hT, wbuf, wsm,
                  Wp + 2 * HDIM * WSTR, CTILE, 32 * WSTR,
                  fb0, fb1, eb0, eb1, pf0, pf1, pe0, pe1, warpid, lane, tid);
        __syncthreads();
        mm256t<1>(Wp + 2 * HDIM * WSTR, b2a + i * HDIM, hT, rT, wbuf, wsm,
                  Wp + 3 * HDIM * WSTR, CTILE, 32 * WSTR,
                  fb0, fb1, eb0, eb1, pf0, pf1, pe0, pe1, warpid, lane, tid);
        __syncthreads();
        mm256t<3>(Wp + 3 * HDIM * WSTR, b2b + i * HDIM, rT, hT, wbuf, wsm,
                  g_wopad + (size_t)i * HDIM * WOSTR, WOTILE, 16 * WOSTR,
                  fb0, fb1, eb0, eb1, pf0, pf1, pe0, pe1, warpid, lane, tid);
        __syncthreads();   // hT = relu(h3), A operand for W_out mma

        // ---- W_out tf32 mma (16-row tiles, tiles 0/1 prefetched by W2b), m16n104 ----
        {
            const float* Wop = g_wopad + (size_t)i * HDIM * WOSTR;
            const float* bop = g_bopad + i * 416;
            const float* nextW1b = (i < LL - 1)
                ? g_wpad + (size_t)(i + 1) * 4 * HDIM * WSTR + HDIM * WSTR : nullptr;
            const int mwp = warpid & 3, nw = warpid >> 2;
            const int m0f = mwp << 4;
            const int n0w = nw * 104;
            const int r = lane >> 2, c = lane & 3;

            float d[13][4];
#pragma unroll
            for (int nt = 0; nt < 13; nt++) {
                int col0 = n0w + nt * 8 + 2 * c;
                float b0 = bop[col0], b1 = bop[col0 + 1];
                d[nt][0] = b0; d[nt][1] = b1; d[nt][2] = b0; d[nt][3] = b1;
            }

#pragma unroll 1
            for (int kb = 0; kb < 16; kb++) {
                const int s = kb & 1;
                // preload ks=0 A fragments before the wait
                unsigned int apre[4];
                {
                    const float* Ab = hT + (kb * 16 + c) * MSTR + m0f + r;
                    apre[0] = __float_as_uint(Ab[0]);
                    apre[1] = __float_as_uint(Ab[8]);
                    apre[2] = __float_as_uint(Ab[4 * MSTR]);
                    apre[3] = __float_as_uint(Ab[4 * MSTR + 8]);
                }
                if (s) { mbar_wait(fb1, pf1); pf1 ^= 1; }
                else   { mbar_wait(fb0, pf0); pf0 ^= 1; }
                const float* wb = wbuf + s * SLOTF;
#pragma unroll
                for (int ks = 0; ks < 2; ks++) {
                    const int k0 = kb * 16 + ks * 8;
                    unsigned int a0, a1, a2, a3;
                    if (ks == 0) {
                        a0 = apre[0]; a1 = apre[1]; a2 = apre[2]; a3 = apre[3];
                    } else {
                        const float* Ab = hT + (k0 + c) * MSTR + m0f + r;
                        a0 = __float_as_uint(Ab[0]);
                        a1 = __float_as_uint(Ab[8]);
                        a2 = __float_as_uint(Ab[4 * MSTR]);
                        a3 = __float_as_uint(Ab[4 * MSTR + 8]);
                    }
                    const float* Bb = wb + (ks * 8 + c) * WOSTR + n0w + r;
#pragma unroll
                    for (int nt = 0; nt < 13; nt++) {
                        unsigned int b0 = __float_as_uint(Bb[nt * 8]);
                        unsigned int b1 = __float_as_uint(Bb[4 * WOSTR + nt * 8]);
                        mma_tf32(d[nt], a0, a1, a2, a3, b0, b1);
                    }
                }
                if (lane == 0) { if (s) mbar_arrive(eb1); else mbar_arrive(eb0); }
                if (tid == 0) {
                    if (kb < 14) {
                        if (s) { mbar_wait_relaxed(eb1, pe1); pe1 ^= 1; }
                        else   { mbar_wait_relaxed(eb0, pe0); pe0 ^= 1; }
                        unsigned int fb = s ? fb1 : fb0;
                        mbar_expect_tx(fb, WOTILE);
                        bulk_g2s(wsm + (unsigned int)(s * SLOTB),
                                 Wop + (kb + 2) * 16 * WOSTR, WOTILE, fb);
                    } else if (nextW1b != nullptr) {
                        if (s) {
                            mbar_wait_relaxed(eb1, pe1); pe1 ^= 1;
                            mbar_expect_tx(fb1, CTILE);
                            bulk_g2s(wsm + (unsigned int)SLOTB,
                                     nextW1b + 32 * WSTR, CTILE, fb1);
                        } else {
                            mbar_wait_relaxed(eb0, pe0); pe0 ^= 1;
                            mbar_expect_tx(fb0, CTILE);
                            bulk_g2s(wsm, nextW1b, CTILE, fb0);
                        }
                    }
                }
            }
            __syncthreads();   // all warps done reading hT before pbuf overwrites it

#pragma unroll
            for (int nt = 0; nt < 13; nt++) {
                const int col0 = n0w + nt * 8 + 2 * c;
                if (col0 < 400) {
                    pbuf[(m0f + r) * PSTR + col0]         = d[nt][0];
                    pbuf[(m0f + r) * PSTR + col0 + 1]     = d[nt][1];
                    pbuf[(m0f + r + 8) * PSTR + col0]     = d[nt][2];
                    pbuf[(m0f + r + 8) * PSTR + col0 + 1] = d[nt][3];
                }
            }
            __syncthreads();

            // ---- spline: warp = packed dim j (actual n = 2j+toff), lane -> 2 rows ----
            const int n  = 2 * warpid + toff;
            const int m0 = lane << 1;
            float ldv[2];
#pragma unroll
            for (int mi = 0; mi < 2; mi++) {
                float pr[PP];
                const float* psrc = pbuf + (m0 + mi) * PSTR + warpid * PP;
#pragma unroll
                for (int p = 0; p < PP; p++) pr[p] = psrc[p];
                float xv = xsT[n * MSTR + m0 + mi];
                float2 rr = rqs_eval(pr, xv, splOff);
                xsT[n * MSTR + m0 + mi] = rr.x;
                ldv[mi] = rr.y;
            }
            atomicAdd(&lds_s[m0],     ldv[0]);
            atomicAdd(&lds_s[m0 + 1], ldv[1]);
        }
        __syncthreads();
    }

    // ---- final log-prob ----
    if (tid < MT) {
        const int m = tid;
        float s2 = 0.f;
#pragma unroll
        for (int nn = 0; nn < NF; nn++) {
            float v = xsT[nn * MSTR + m];
            s2 = fmaf(v, v, s2);
        }
        float C = 0.f;
        for (int i = 0; i < LL; i++)
            for (int nn = 0; nn < NF; nn++)
                C += __logf(fabsf(sc_scale[i * NF + nn]));
        out[base + m] = -0.5f * s2 - 0.5f * (float)NF * 1.8378770664093453f + lds_s[m] + C;
    }
}

// ---------------------------------------------------------------------------
extern "C" void kernel_launch(void* const* d_in, const int* in_sizes, int n_in,
                              void* d_out, int out_size)
{
    const float* x        = (const float*)d_in[0];
    const float* sc_scale = (const float*)d_in[1];
    const float* sc_shift = (const float*)d_in[2];
    const float* W_in     = (const float*)d_in[3];
    const float* b_in     = (const float*)d_in[4];
    const float* W1a      = (const float*)d_in[5];
    const float* b1a      = (const float*)d_in[6];
    const float* W1b      = (const float*)d_in[7];
    const float* b1b      = (const float*)d_in[8];
    const float* W2a      = (const float*)d_in[9];
    const float* b2a      = (const float*)d_in[10];
    const float* W2b      = (const float*)d_in[11];
    const float* b2b      = (const float*)d_in[12];
    const float* W_out    = (const float*)d_in[13];
    const float* b_out    = (const float*)d_in[14];
    const int*   perms    = (const int*)d_in[15];

    // prep: pad/convert weights + fold W1a into the low-rank input path
    {
        const long long totalA = (long long)LL * 4 * HDIM * WSTR;
        prep_weights<<<(int)((totalA + 255) / 256), 256>>>(W1a, W1b, W2a, W2b);
        const long long totalO = (long long)LL * HDIM * WOSTR;
        prep_wout<<<(int)((totalO + 255) / 256), 256>>>(W_out, b_out);
        const int totalF = LL * 16 * HDIM;
        prep_fused<<<(totalF + 255) / 256, 256>>>(W_in, b_in, W1a, b1a);
    }

    const int B = in_sizes[0] / NF;
    const int grid = B / MT;
    const size_t smem = (size_t)(2 * HDIM * MSTR + 2 * SLOTF + NF * MSTR + MT + 8)
                        * sizeof(float);

    cudaFuncSetAttribute(rqs_flow_kernel,
                         cudaFuncAttributeMaxDynamicSharedMemorySize, (int)smem);

    rqs_flow_kernel<<<grid, NTHREADS, smem>>>(
        x, sc_scale, sc_shift, W_in, b_in, b1b, b2a, b2b,
        perms, (float*)d_out);
}

// round 17
// speedup vs baseline: 1.3575x; 1.3262x over previous
#include <cuda_runtime.h>
#include <cuda_fp16.h>
#include <cstdint>

#define NF 32
#define LL 8
#define HDIM 256
#define KBINS 8
#define PP 25
#define NP 800
#define MT 64
#define NTHREADS 512
#define MSTR 72          // xsT (fp32) stride
#define AST 280          // activation row stride in halves (256 used + 24 pad); 140 u32
#define WROWH 40         // W tile row stride in halves (32 used + 8 pad); 20 u32
#define CT_H (256 * WROWH)   // 10240 halves per conditioner k-tile
#define WO_H (448 * WROWH)   // 17920 halves per W_out k-tile
#define PSTR 449

#define RMINF (-10.0f)
#define RMAXF (10.0f)
#define MINBIN (1e-4f)
#define MINSLOPE (1e-4f)

#define CTILEB  20480u   // bytes per conditioner tile
#define WOTILEB 35840u   // bytes per W_out tile
#define SLOTB   35840u   // slot byte stride
#define SLOTH   17920    // slot stride in halves

typedef unsigned long long u64;
typedef unsigned int u32;

// fp16 packed weights (k-tiled [kb][n][40h]) + fused W_in@W1a fp32 path
__device__ __align__(16) __half g_wpad_h[(size_t)LL * 4 * 8 * CT_H];
__device__ __align__(16) __half g_wopad_h[(size_t)LL * 8 * WO_H];
__device__ __align__(16) float  g_bopad[LL * 448];
__device__ __align__(16) float  g_wf[LL * 16 * HDIM];
__device__ __align__(16) float  g_bf[LL * HDIM];

__device__ __forceinline__ u64 pack2(float lo, float hi) {
    u64 r; asm("mov.b64 %0, {%1,%2};" : "=l"(r) : "f"(lo), "f"(hi)); return r;
}
__device__ __forceinline__ float2 unpack2(u64 v) {
    float2 r; asm("mov.b64 {%0,%1}, %2;" : "=f"(r.x), "=f"(r.y) : "l"(v)); return r;
}
__device__ __forceinline__ void fma2(u64& d, u64 a, u64 b) {
    asm("fma.rn.f32x2 %0, %1, %2, %0;" : "+l"(d) : "l"(a), "l"(b));
}
__device__ __forceinline__ u32 pack_h2(float lo, float hi) {
    __half2 h = __floats2half2_rn(lo, hi);
    return *reinterpret_cast<u32*>(&h);
}
__device__ __forceinline__ float2 unpack_h2(u32 v) {
    __half2 h = *reinterpret_cast<__half2*>(&v);
    return __half22float2(h);
}
__device__ __forceinline__ void mma_f16(float* d, u32 a0, u32 a1, u32 a2, u32 a3,
                                        u32 b0, u32 b1) {
    asm("mma.sync.aligned.m16n8k16.row.col.f32.f16.f16.f32 "
        "{%0,%1,%2,%3}, {%4,%5,%6,%7}, {%8,%9}, {%0,%1,%2,%3};"
        : "+f"(d[0]), "+f"(d[1]), "+f"(d[2]), "+f"(d[3])
        : "r"(a0), "r"(a1), "r"(a2), "r"(a3), "r"(b0), "r"(b1));
}

// ---- mbarrier + 1D bulk-async helpers ----
__device__ __forceinline__ void mbar_init(u32 mbar, u32 cnt) {
    asm volatile("mbarrier.init.shared.b64 [%0], %1;" :: "r"(mbar), "r"(cnt) : "memory");
}
__device__ __forceinline__ void mbar_expect_tx(u32 mbar, u32 bytes) {
    asm volatile("mbarrier.arrive.expect_tx.shared.b64 _, [%0], %1;"
                 :: "r"(mbar), "r"(bytes) : "memory");
}
__device__ __forceinline__ void mbar_arrive(u32 mbar) {
    asm volatile("mbarrier.arrive.shared.b64 _, [%0];" :: "r"(mbar) : "memory");
}
__device__ __forceinline__ void bulk_g2s(u32 dst, const void* src, u32 bytes, u32 mbar) {
    asm volatile("cp.async.bulk.shared::cluster.global.mbarrier::complete_tx::bytes "
                 "[%0], [%1], %2, [%3];"
                 :: "r"(dst), "l"(src), "r"(bytes), "r"(mbar) : "memory");
}
__device__ __forceinline__ void mbar_wait(u32 mbar, int parity) {
    u32 done;
    asm volatile(
        "{\n\t.reg .pred p;\n\t"
        "mbarrier.try_wait.parity.acquire.cta.shared::cta.b64 p, [%1], %2;\n\t"
        "selp.b32 %0, 1, 0, p;\n\t}"
        : "=r"(done) : "r"(mbar), "r"(parity) : "memory");
    if (!done) {
        asm volatile(
            "{\n\t.reg .pred P1;\n\t"
            "WAIT_LOOP_%=:\n\t"
            "mbarrier.try_wait.parity.acquire.cta.shared::cta.b64 P1, [%0], %1, 0x989680;\n\t"
            "@P1 bra.uni WAIT_DONE_%=;\n\t"
            "bra.uni WAIT_LOOP_%=;\n\t"
            "WAIT_DONE_%=:\n\t}"
            :: "r"(mbar), "r"(parity) : "memory");
    }
}
__device__ __forceinline__ void mbar_wait_relaxed(u32 mbar, int parity) {
    u32 done;
    asm volatile(
        "{\n\t.reg .pred p;\n\t"
        "mbarrier.try_wait.parity.relaxed.cta.shared::cta.b64 p, [%1], %2;\n\t"
        "selp.b32 %0, 1, 0, p;\n\t}"
        : "=r"(done) : "r"(mbar), "r"(parity) : "memory");
    if (!done) {
        asm volatile(
            "{\n\t.reg .pred P1;\n\t"
            "WAIT_LOOP_%=:\n\t"
            "mbarrier.try_wait.parity.relaxed.cta.shared::cta.b64 P1, [%0], %1, 0x989680;\n\t"
            "@P1 bra.uni WAIT_DONE_%=;\n\t"
            "bra.uni WAIT_LOOP_%=;\n\t"
            "WAIT_DONE_%=:\n\t}"
            :: "r"(mbar), "r"(parity) : "memory");
    }
}

// ---------------------------------------------------------------------------
// Prep: fp16-convert weights into k-tiled [kb][n][WROWH] layout.
// B operand layout: row n, halves = k (transposed from source [k][n]).
// ---------------------------------------------------------------------------
extern "C" __global__ void prep_weights(const float* __restrict__ W1a,
                                        const float* __restrict__ W1b,
                                        const float* __restrict__ W2a,
                                        const float* __restrict__ W2b)
{
    long long idx = (long long)blockIdx.x * blockDim.x + threadIdx.x;
    const long long total = (long long)LL * 4 * 8 * CT_H;
    if (idx >= total) return;
    int h  = (int)(idx % CT_H);
    long long t = idx / CT_H;
    int kb = (int)(t % 8);  t /= 8;
    int j  = (int)(t % 4);
    int i  = (int)(t / 4);
    int n  = h / WROWH;
    int kc = h % WROWH;
    float v = 0.f;
    if (kc < 32) {
        int k = kb * 32 + kc;
        const float* src = (j == 0 ? W1a : j == 1 ? W1b : j == 2 ? W2a : W2b);
        v = src[(size_t)i * HDIM * HDIM + (size_t)k * HDIM + n];
    }
    g_wpad_h[idx] = __float2half_rn(v);
}

// W_out packed 448 cols (dim j -> cols [28j,28j+25)), k-tiled, fp16.
extern "C" __global__ void prep_wout(const float* __restrict__ Wo,
                                     const float* __restrict__ bo)
{
    long long idx = (long long)blockIdx.x * blockDim.x + threadIdx.x;
    const long long totalW = (long long)LL * 8 * WO_H;
    if (idx < totalW) {
        int h  = (int)(idx % WO_H);
        long long t = idx / WO_H;
        int kb = (int)(t % 8);
        int i  = (int)(t / 8);
        int n  = h / WROWH;
        int kc = h % WROWH;
        int toff = i & 1;
        float v = 0.f;
        if (kc < 32) {
            int k = kb * 32 + kc;
            int jj = n / 28, p = n - jj * 28;
            if (p < PP)
                v = Wo[(size_t)i * HDIM * NP + (size_t)k * NP + (2 * jj + toff) * PP + p];
        }
        g_wopad_h[idx] = __float2half_rn(v);
    }
    if (idx < LL * 448) {
        int i = (int)(idx / 448), col = (int)(idx % 448);
        int toff = i & 1;
        int jj = col / 28, p = col - jj * 28;
        float v = 0.f;
        if (p < PP) v = bo[i * NP + (2 * jj + toff) * PP + p];
        g_bopad[idx] = v;
    }
}

extern "C" __global__ void prep_fused(const float* __restrict__ W_in,
                                      const float* __restrict__ b_in,
                                      const float* __restrict__ W1a,
                                      const float* __restrict__ b1a)
{
    int idx = blockIdx.x * blockDim.x + threadIdx.x;
    const int totalW = LL * 16 * HDIM;
    if (idx < totalW) {
        int c = idx % HDIM;
        int t = idx / HDIM;
        int k = t % 16;
        int i = t / 16;
        int koff = (i & 1) ? 0 : 1;
        int n = 2 * k + koff;
        const float* wi = W_in + ((size_t)i * NF + n) * HDIM;
        const float* wa = W1a + (size_t)i * HDIM * HDIM + c;
        float s = 0.f;
        for (int j = 0; j < HDIM; j++) s = fmaf(wi[j], wa[(size_t)j * HDIM], s);
        g_wf[idx] = s;
    }
    if (idx < LL * HDIM) {
        int c = idx % HDIM;
        int i = idx / HDIM;
        const float* bi = b_in + i * HDIM;
        const float* wa = W1a + (size_t)i * HDIM * HDIM + c;
        float s = b1a[i * HDIM + c];
        for (int j = 0; j < HDIM; j++) s = fmaf(bi[j], wa[(size_t)j * HDIM], s);
        g_bf[idx] = s;
    }
}

// ---------------------------------------------------------------------------
// mmIn row-parallel: warp -> 4 rows, lane L -> col-pairs {2L+64p}.
// Output fp16 [m][k] stride AST. STORE==1: relu before store.
// ---------------------------------------------------------------------------
template <int STORE, int RSTRIDE>
__device__ __forceinline__ void mmInH(const float* __restrict__ W,
                                      const float* __restrict__ bi,
                                      const float* __restrict__ xsT,
                                      __half* __restrict__ DT,
                                      int warpid, int lane, int rowOff)
{
    const int mrow = warpid << 2;
    u64 acc[4][4];
#pragma unroll
    for (int p = 0; p < 4; p++) {
        u64 b = *reinterpret_cast<const u64*>(bi + 2 * lane + 64 * p);
        acc[0][p] = b; acc[1][p] = b; acc[2][p] = b; acc[3][p] = b;
    }
#pragma unroll
    for (int k = 0; k < 16; k++) {
        const int n = 2 * k + rowOff;
        const int wr = (RSTRIDE == 2) ? n : k;
        float xv[4];
#pragma unroll
        for (int rr = 0; rr < 4; rr++) xv[rr] = xsT[n * MSTR + mrow + rr];
        u64 ax[4];
#pragma unroll
        for (int rr = 0; rr < 4; rr++) ax[rr] = pack2(xv[rr], xv[rr]);
#pragma unroll
        for (int p = 0; p < 4; p++) {
            u64 w = *reinterpret_cast<const u64*>(W + wr * HDIM + 2 * lane + 64 * p);
#pragma unroll
            for (int rr = 0; rr < 4; rr++) fma2(acc[rr][p], ax[rr], w);
        }
    }
#pragma unroll
    for (int rr = 0; rr < 4; rr++) {
#pragma unroll
        for (int p = 0; p < 4; p++) {
            float2 v = unpack2(acc[rr][p]);
            if (STORE == 1) { v.x = fmaxf(v.x, 0.f); v.y = fmaxf(v.y, 0.f); }
            *reinterpret_cast<u32*>(DT + (mrow + rr) * AST + 2 * lane + 64 * p) =
                pack_h2(v.x, v.y);
        }
    }
}

// ---------------------------------------------------------------------------
// Conditioner GEMM, fp16 m16n8k16, m32n32 warps (2m x 8n), 8 k-tiles of k32.
// Tiles 0/1 pre-issued. kb<6 refill; kb 6/7 prefetch nextW tiles 0/1.
// MODE 1: D=relu; 2: D=D+relu; 3: D=relu(D+relu).  D/A fp16 [m][k].
// ---------------------------------------------------------------------------
template <int MODE>
__device__ __forceinline__ void mm256h(const __half* __restrict__ Wt,
                                       const float* __restrict__ bias,
                                       const __half* __restrict__ AT,
                                       __half* __restrict__ DT,
                                       const __half* __restrict__ wbuf, u32 wsm,
                                       const __half* __restrict__ nextW,
                                       u32 nextBytes, int nextT1H,
                                       u32 fb0, u32 fb1, u32 eb0, u32 eb1,
                                       int& pf0, int& pf1, int& pe0, int& pe1,
                                       int warpid, int lane, int tid)
{
    const int mwp = warpid & 1, nw = warpid >> 1;
    const int m0 = mwp << 5;
    const int n0w = nw << 5;
    const int r = lane >> 2, c = lane & 3;

    float d[2][4][4];
#pragma unroll
    for (int nt = 0; nt < 4; nt++) {
        float b0 = bias[n0w + nt * 8 + 2 * c];
        float b1 = bias[n0w + nt * 8 + 2 * c + 1];
#pragma unroll
        for (int mf = 0; mf < 2; mf++) {
            d[mf][nt][0] = b0; d[mf][nt][1] = b1;
            d[mf][nt][2] = b0; d[mf][nt][3] = b1;
        }
    }

#pragma unroll 1
    for (int kb = 0; kb < 8; kb++) {
        const int s = kb & 1;
        // preload ks=0 A fragments (stable source)
        u32 apre[2][4];
#pragma unroll
        for (int mf = 0; mf < 2; mf++) {
            const __half* Ab  = AT + (m0 + mf * 16 + r) * AST + kb * 32;
            const __half* Ab8 = Ab + 8 * AST;
            apre[mf][0] = *reinterpret_cast<const u32*>(Ab  + 2 * c);
            apre[mf][1] = *reinterpret_cast<const u32*>(Ab8 + 2 * c);
            apre[mf][2] = *reinterpret_cast<const u32*>(Ab  + 8 + 2 * c);
            apre[mf][3] = *reinterpret_cast<const u32*>(Ab8 + 8 + 2 * c);
        }
        if (s) { mbar_wait(fb1, pf1); pf1 ^= 1; }
        else   { mbar_wait(fb0, pf0); pf0 ^= 1; }
        const __half* wb = wbuf + s * SLOTH;
#pragma unroll
        for (int ks = 0; ks < 2; ks++) {
            u32 a[2][4];
            if (ks == 0) {
#pragma unroll
                for (int mf = 0; mf < 2; mf++)
#pragma unroll
                    for (int q = 0; q < 4; q++) a[mf][q] = apre[mf][q];
            } else {
#pragma unroll
                for (int mf = 0; mf < 2; mf++) {
                    const __half* Ab  = AT + (m0 + mf * 16 + r) * AST + kb * 32 + 16;
                    const __half* Ab8 = Ab + 8 * AST;
                    a[mf][0] = *reinterpret_cast<const u32*>(Ab  + 2 * c);
                    a[mf][1] = *reinterpret_cast<const u32*>(Ab8 + 2 * c);
                    a[mf][2] = *reinterpret_cast<const u32*>(Ab  + 8 + 2 * c);
                    a[mf][3] = *reinterpret_cast<const u32*>(Ab8 + 8 + 2 * c);
                }
            }
#pragma unroll
            for (int nt = 0; nt < 4; nt++) {
                const __half* Bb = wb + (n0w + nt * 8 + r) * WROWH + ks * 16;
                u32 b0 = *reinterpret_cast<const u32*>(Bb + 2 * c);
                u32 b1 = *reinterpret_cast<const u32*>(Bb + 8 + 2 * c);
                mma_f16(d[0][nt], a[0][0], a[0][1], a[0][2], a[0][3], b0, b1);
                mma_f16(d[1][nt], a[1][0], a[1][1], a[1][2], a[1][3], b0, b1);
            }
        }
        if (lane == 0) { if (s) mbar_arrive(eb1); else mbar_arrive(eb0); }
        if (tid == 0) {
            if (kb < 6) {
                if (s) { mbar_wait_relaxed(eb1, pe1); pe1 ^= 1; }
                else   { mbar_wait_relaxed(eb0, pe0); pe0 ^= 1; }
                u32 fb = s ? fb1 : fb0;
                mbar_expect_tx(fb, CTILEB);
                bulk_g2s(wsm + (u32)(s * SLOTB), Wt + (kb + 2) * CT_H, CTILEB, fb);
            } else if (nextW != nullptr) {
                if (s) {
                    mbar_wait_relaxed(eb1, pe1); pe1 ^= 1;
                    mbar_expect_tx(fb1, nextBytes);
                    bulk_g2s(wsm + (u32)SLOTB, nextW + nextT1H, nextBytes, fb1);
                } else {
                    mbar_wait_relaxed(eb0, pe0); pe0 ^= 1;
                    mbar_expect_tx(fb0, nextBytes);
                    bulk_g2s(wsm, nextW, nextBytes, fb0);
                }
            }
        }
    }
    // epilogue: fp16 read-modify-write of DT
#pragma unroll
    for (int mf = 0; mf < 2; mf++) {
#pragma unroll
        for (int nt = 0; nt < 4; nt++) {
            const int col0 = n0w + nt * 8 + 2 * c;
            const int row = m0 + mf * 16 + r;
            u32* p0 = reinterpret_cast<u32*>(DT + row * AST + col0);
            u32* p1 = reinterpret_cast<u32*>(DT + (row + 8) * AST + col0);
            float r0 = fmaxf(d[mf][nt][0], 0.f), r1 = fmaxf(d[mf][nt][1], 0.f);
            float r2 = fmaxf(d[mf][nt][2], 0.f), r3 = fmaxf(d[mf][nt][3], 0.f);
            if (MODE == 1) {
                *p0 = pack_h2(r0, r1);
                *p1 = pack_h2(r2, r3);
            } else {
                float2 o0 = unpack_h2(*p0);
                float2 o1 = unpack_h2(*p1);
                float v0 = o0.x + r0, v1 = o0.y + r1;
                float v2 = o1.x + r2, v3 = o1.y + r3;
                if (MODE == 3) {
                    v0 = fmaxf(v0, 0.f); v1 = fmaxf(v1, 0.f);
                    v2 = fmaxf(v2, 0.f); v3 = fmaxf(v3, 0.f);
                }
                *p0 = pack_h2(v0, v1);
                *p1 = pack_h2(v2, v3);
            }
        }
    }
}

// ---------------------------------------------------------------------------
// Rational-quadratic spline (fp32, unchanged).
// ---------------------------------------------------------------------------
__device__ __forceinline__ float2 rqs_eval(const float* __restrict__ p, float xv, float splOff)
{
    float w[KBINS], hh[KBINS], d[KBINS + 1];
    float mw = p[0], mh = p[8];
#pragma unroll
    for (int j = 1; j < KBINS; j++) { mw = fmaxf(mw, p[j]); mh = fmaxf(mh, p[8 + j]); }
    float sw = 0.f, sh = 0.f;
#pragma unroll
    for (int j = 0; j < KBINS; j++) {
        w[j]  = __expf(p[j] - mw);       sw += w[j];
        hh[j] = __expf(p[8 + j] - mh);   sh += hh[j];
    }
    const float span = (RMAXF - RMINF) - KBINS * MINBIN;
    const float sclw = __fdividef(span, sw);
    const float sclh = __fdividef(span, sh);
#pragma unroll
    for (int j = 0; j < KBINS + 1; j++) {
        float v = p[16 + j] + splOff;
        d[j] = ((v > 15.f) ? v : __logf(1.f + __expf(v))) + MINSLOPE;
    }
    float xp[KBINS + 1], yp[KBINS + 1];
    xp[0] = RMINF; yp[0] = RMINF;
#pragma unroll
    for (int j = 0; j < KBINS; j++) {
        xp[j + 1] = xp[j] + fmaf(w[j], sclw, MINBIN);
        yp[j + 1] = yp[j] + fmaf(hh[j], sclh, MINBIN);
    }
    float xc = fminf(fmaxf(xv, RMINF), RMAXF);
    int idx = 0;
#pragma unroll
    for (int j = 1; j <= KBINS; j++) idx += (xc >= xp[j]) ? 1 : 0;
    idx = min(idx, KBINS - 1);
    float xk = xp[0], xk1 = xp[1], yk = yp[0], yk1 = yp[1], dk = d[0], dk1 = d[1];
#pragma unroll
    for (int j = 1; j < KBINS; j++) {
        if (idx == j) { xk = xp[j]; xk1 = xp[j + 1]; yk = yp[j]; yk1 = yp[j + 1]; dk = d[j]; dk1 = d[j + 1]; }
    }
    float bw = xk1 - xk;
    float bh = yk1 - yk;
    float s = __fdividef(bh, bw);
    float z = fminf(fmaxf(__fdividef(xc - xk, bw), 0.f), 1.f);
    float omz = 1.f - z;
    float zz = z * omz;
    float denom = fmaf(dk1 + dk - 2.f * s, zz, s);
    float y = yk + bh * __fdividef(fmaf(s * z, z, dk * zz), denom);
    float num = fmaf(dk1 * z, z, fmaf(2.f * s, zz, dk * omz * omz));
    float ld = 2.f * __logf(s) + __logf(num) - 2.f * __logf(denom);
    bool inside = (xv > RMINF) && (xv < RMAXF);
    return make_float2(inside ? y : xv, inside ? ld : 0.f);
}

// ---------------------------------------------------------------------------
extern "C" __global__ void __launch_bounds__(NTHREADS, 1)
rqs_flow_kernel(const float* __restrict__ x,
                const float* __restrict__ sc_scale,
                const float* __restrict__ sc_shift,
                const float* __restrict__ W_in,  const float* __restrict__ b_in,
                const float* __restrict__ b1b,
                const float* __restrict__ b2a,   const float* __restrict__ b2b,
                const int* __restrict__ perms,
                float* __restrict__ out)
{
    extern __shared__ __align__(16) char smem[];
    __half* hT     = reinterpret_cast<__half*>(smem);                 // 64*AST halves
    __half* rT     = hT + MT * AST;                                   // 64*AST
    __half* wbuf   = rT + MT * AST;                                   // 2 * SLOTH
    float*  xsT    = reinterpret_cast<float*>(wbuf + 2 * SLOTH);      // 32*MSTR fp32
    float*  lds_s  = xsT + NF * MSTR;                                 // 64
    float*  mbm    = lds_s + MT;                                      // 4 mbarriers
    float*  pbuf   = reinterpret_cast<float*>(smem);                  // 64 x PSTR (aliases)

    const int tid    = threadIdx.x;
    const int warpid = tid >> 5;
    const int lane   = tid & 31;
    const long long base = (long long)blockIdx.x * MT;
    const u32 wsm = (u32)__cvta_generic_to_shared(wbuf);
    const u32 fb0 = (u32)__cvta_generic_to_shared(mbm);
    const u32 fb1 = fb0 + 8;
    const u32 eb0 = fb0 + 16;
    const u32 eb1 = fb0 + 24;
    int pf0 = 0, pf1 = 0, pe0 = 0, pe1 = 0;

    // load x transposed (fp32): xsT[n][m]
    {
        const int m  = tid >> 3;
        const int n4 = (tid & 7) << 2;
        float4 gx = *reinterpret_cast<const float4*>(x + (base + m) * NF + n4);
        xsT[(n4 + 0) * MSTR + m] = gx.x;
        xsT[(n4 + 1) * MSTR + m] = gx.y;
        xsT[(n4 + 2) * MSTR + m] = gx.z;
        xsT[(n4 + 3) * MSTR + m] = gx.w;
    }
    if (tid < MT) lds_s[tid] = 0.f;
    if (tid == 0) {
        mbar_init(fb0, 1); mbar_init(fb1, 1);
        mbar_init(eb0, 16); mbar_init(eb1, 16);
    }
    const float splOff = logf(expm1f(1.0f - MINSLOPE));
    __syncthreads();

    // prologue: layer 0 W1b tiles 0/1
    if (tid == 0) {
        const __half* W1b0 = g_wpad_h + (size_t)1 * 8 * CT_H;
        mbar_expect_tx(fb0, CTILEB);
        bulk_g2s(wsm, W1b0, CTILEB, fb0);
        mbar_expect_tx(fb1, CTILEB);
        bulk_g2s(wsm + SLOTB, W1b0 + CT_H, CTILEB, fb1);
    }

    for (int i = 0; i < LL; i++) {
        const int koff = (i & 1) ? 0 : 1;
        const int toff = 1 - koff;

        // ---- permute + affine (fp32) ----
        {
            const int*   pm  = perms    + i * NF;
            const float* scs = sc_scale + i * NF;
            const float* sch = sc_shift + i * NF;
            const int n  = tid >> 4;
            const int ms = (tid & 15) << 2;
            const float s  = scs[n];
            const float sh = sch[n];
            const int   pn = pm[n];
            float tmp[4];
#pragma unroll
            for (int q = 0; q < 4; q++)
                tmp[q] = fmaf(xsT[pn * MSTR + ms + q], s, sh);
            __syncthreads();
#pragma unroll
            for (int q = 0; q < 4; q++)
                xsT[n * MSTR + ms + q] = tmp[q];
            __syncthreads();
        }

        // ---- input stage: hT = h (fp16), rT = relu(mx@Wf+bf) (fp16) ----
        mmInH<0, 2>(W_in + i * NF * HDIM, b_in + i * HDIM, xsT, hT, warpid, lane, koff);
        mmInH<1, 1>(g_wf + i * 16 * HDIM, g_bf + i * HDIM, xsT, rT, warpid, lane, koff);
        __syncthreads();

        const __half* Wp = g_wpad_h + (size_t)i * 4 * 8 * CT_H;
        // W1b: hT = h + relu(rT @ W1b + b1b)
        mm256h<2>(Wp + (size_t)1 * 8 * CT_H, b1b + i * HDIM, rT, hT, wbuf, wsm,
                  Wp + (size_t)2 * 8 * CT_H, CTILEB, CT_H,
                  fb0, fb1, eb0, eb1, pf0, pf1, pe0, pe1, warpid, lane, tid);
        __syncthreads();
        mm256h<1>(Wp + (size_t)2 * 8 * CT_H, b2a + i * HDIM, hT, rT, wbuf, wsm,
                  Wp + (size_t)3 * 8 * CT_H, CTILEB, CT_H,
                  fb0, fb1, eb0, eb1, pf0, pf1, pe0, pe1, warpid, lane, tid);
        __syncthreads();
        mm256h<3>(Wp + (size_t)3 * 8 * CT_H, b2b + i * HDIM, rT, hT, wbuf, wsm,
                  g_wopad_h + (size_t)i * 8 * WO_H, WOTILEB, WO_H,
                  fb0, fb1, eb0, eb1, pf0, pf1, pe0, pe1, warpid, lane, tid);
        __syncthreads();   // hT = relu(h3) fp16: A for W_out

        // ---- W_out fp16 mma, m32n56 warps (2m x 8n), 8 k-tiles ----
        {
            const __half* Wot = g_wopad_h + (size_t)i * 8 * WO_H;
            const float*  bop = g_bopad + i * 448;
            const int mwp = warpid & 1, nw = warpid >> 1;
            const int m0f = mwp << 5;
            const int n0w = nw * 56;
            const int r = lane >> 2, c = lane & 3;

            float d[2][7][4];
#pragma unroll
            for (int nt = 0; nt < 7; nt++) {
                int col0 = n0w + nt * 8 + 2 * c;
                float b0 = bop[col0], b1 = bop[col0 + 1];
#pragma unroll
                for (int mf = 0; mf < 2; mf++) {
                    d[mf][nt][0] = b0; d[mf][nt][1] = b1;
                    d[mf][nt][2] = b0; d[mf][nt][3] = b1;
                }
            }

#pragma unroll 1
            for (int kb = 0; kb < 8; kb++) {
                const int s = kb & 1;
                u32 apre[2][4];
#pragma unroll
                for (int mf = 0; mf < 2; mf++) {
                    const __half* Ab  = hT + (m0f + mf * 16 + r) * AST + kb * 32;
                    const __half* Ab8 = Ab + 8 * AST;
                    apre[mf][0] = *reinterpret_cast<const u32*>(Ab  + 2 * c);
                    apre[mf][1] = *reinterpret_cast<const u32*>(Ab8 + 2 * c);
                    apre[mf][2] = *reinterpret_cast<const u32*>(Ab  + 8 + 2 * c);
                    apre[mf][3] = *reinterpret_cast<const u32*>(Ab8 + 8 + 2 * c);
                }
                if (s) { mbar_wait(fb1, pf1); pf1 ^= 1; }
                else   { mbar_wait(fb0, pf0); pf0 ^= 1; }
                const __half* wb = wbuf + s * SLOTH;
#pragma unroll
                for (int ks = 0; ks < 2; ks++) {
                    u32 a[2][4];
                    if (ks == 0) {
#pragma unroll
                        for (int mf = 0; mf < 2; mf++)
#pragma unroll
                            for (int q = 0; q < 4; q++) a[mf][q] = apre[mf][q];
                    } else {
#pragma unroll
                        for (int mf = 0; mf < 2; mf++) {
                            const __half* Ab  = hT + (m0f + mf * 16 + r) * AST + kb * 32 + 16;
                            const __half* Ab8 = Ab + 8 * AST;
                            a[mf][0] = *reinterpret_cast<const u32*>(Ab  + 2 * c);
                            a[mf][1] = *reinterpret_cast<const u32*>(Ab8 + 2 * c);
                            a[mf][2] = *reinterpret_cast<const u32*>(Ab  + 8 + 2 * c);
                            a[mf][3] = *reinterpret_cast<const u32*>(Ab8 + 8 + 2 * c);
                        }
                    }
#pragma unroll
                    for (int nt = 0; nt < 7; nt++) {
                        const __half* Bb = wb + (n0w + nt * 8 + r) * WROWH + ks * 16;
                        u32 b0 = *reinterpret_cast<const u32*>(Bb + 2 * c);
                        u32 b1 = *reinterpret_cast<const u32*>(Bb + 8 + 2 * c);
                        mma_f16(d[0][nt], a[0][0], a[0][1], a[0][2], a[0][3], b0, b1);
                        mma_f16(d[1][nt], a[1][0], a[1][1], a[1][2], a[1][3], b0, b1);
                    }
                }
                if (lane == 0) { if (s) mbar_arrive(eb1); else mbar_arrive(eb0); }
                if (tid == 0 && kb < 6) {
                    if (s) { mbar_wait_relaxed(eb1, pe1); pe1 ^= 1; }
                    else   { mbar_wait_relaxed(eb0, pe0); pe0 ^= 1; }
                    u32 fb = s ? fb1 : fb0;
                    mbar_expect_tx(fb, WOTILEB);
                    bulk_g2s(wsm + (u32)(s * SLOTB), Wot + (kb + 2) * WO_H, WOTILEB, fb);
                }
            }
            __syncthreads();   // hT dead; pbuf may now alias smem (incl. W slots)

            // fragments -> pbuf fp32 [m][448] stride PSTR
#pragma unroll
            for (int mf = 0; mf < 2; mf++) {
#pragma unroll
                for (int nt = 0; nt < 7; nt++) {
                    const int col0 = n0w + nt * 8 + 2 * c;
                    const int row = m0f + mf * 16 + r;
                    pbuf[row * PSTR + col0]           = d[mf][nt][0];
                    pbuf[row * PSTR + col0 + 1]       = d[mf][nt][1];
                    pbuf[(row + 8) * PSTR + col0]     = d[mf][nt][2];
                    pbuf[(row + 8) * PSTR + col0 + 1] = d[mf][nt][3];
                }
            }
            __syncthreads();

            // ---- spline: warp = dim j, lane -> 2 rows ----
            const int n  = 2 * warpid + toff;
            const int m0 = lane << 1;
            float ldv[2];
#pragma unroll
            for (int mi = 0; mi < 2; mi++) {
                float pr[PP];
                const float* psrc = pbuf + (m0 + mi) * PSTR + warpid * 28;
#pragma unroll
                for (int p = 0; p < PP; p++) pr[p] = psrc[p];
                float xv = xsT[n * MSTR + m0 + mi];
                float2 rr = rqs_eval(pr, xv, splOff);
                xsT[n * MSTR + m0 + mi] = rr.x;
                ldv[mi] = rr.y;
            }
            atomicAdd(&lds_s[m0],     ldv[0]);
            atomicAdd(&lds_s[m0 + 1], ldv[1]);
        }
        __syncthreads();   // spline/pbuf done before slots are refilled

        // issue next layer's W1b tiles 0/1 (slots are free: pbuf consumers synced)
        if (tid == 0 && i < LL - 1) {
            const __half* nxt = g_wpad_h + ((size_t)(i + 1) * 4 + 1) * 8 * CT_H;
            mbar_wait_relaxed(eb0, pe0); pe0 ^= 1;
            mbar_expect_tx(fb0, CTILEB);
            bulk_g2s(wsm, nxt, CTILEB, fb0);
            mbar_wait_relaxed(eb1, pe1); pe1 ^= 1;
            mbar_expect_tx(fb1, CTILEB);
            bulk_g2s(wsm + SLOTB, nxt + CT_H, CTILEB, fb1);
        }
    }

    // ---- final log-prob ----
    if (tid < MT) {
        const int m = tid;
        float s2 = 0.f;
#pragma unroll
        for (int nn = 0; nn < NF; nn++) {
            float v = xsT[nn * MSTR + m];
            s2 = fmaf(v, v, s2);
        }
        float C = 0.f;
        for (int i = 0; i < LL; i++)
            for (int nn = 0; nn < NF; nn++)
                C += __logf(fabsf(sc_scale[i * NF + nn]));
        out[base + m] = -0.5f * s2 - 0.5f * (float)NF * 1.8378770664093453f + lds_s[m] + C;
    }
}

// ---------------------------------------------------------------------------
extern "C" void kernel_launch(void* const* d_in, const int* in_sizes, int n_in,
                              void* d_out, int out_size)
{
    const float* x        = (const float*)d_in[0];
    const float* sc_scale = (const float*)d_in[1];
    const float* sc_shift = (const float*)d_in[2];
    const float* W_in     = (const float*)d_in[3];
    const float* b_in     = (const float*)d_in[4];
    const float* W1a      = (const float*)d_in[5];
    const float* b1a      = (const float*)d_in[6];
    const float* W1b      = (const float*)d_in[7];
    const float* b1b      = (const float*)d_in[8];
    const float* W2a      = (const float*)d_in[9];
    const float* b2a      = (const float*)d_in[10];
    const float* W2b      = (const float*)d_in[11];
    const float* b2b      = (const float*)d_in[12];
    const float* W_out    = (const float*)d_in[13];
    const float* b_out    = (const float*)d_in[14];
    const int*   perms    = (const int*)d_in[15];

    {
        const long long totalA = (long long)LL * 4 * 8 * CT_H;
        prep_weights<<<(int)((totalA + 255) / 256), 256>>>(W1a, W1b, W2a, W2b);
        const long long totalO = (long long)LL * 8 * WO_H;
        prep_wout<<<(int)((totalO + 255) / 256), 256>>>(W_out, b_out);
        const int totalF = LL * 16 * HDIM;
        prep_fused<<<(totalF + 255) / 256, 256>>>(W_in, b_in, W1a, b1a);
    }

    const int B = in_sizes[0] / NF;
    const int grid = B / MT;
    // hT + rT (fp16) + 2 W slots + xsT + lds + mbarriers
    const size_t smemB = (size_t)(2 * MT * AST + 2 * SLOTH) * 2
                       + (size_t)(NF * MSTR + MT + 8) * 4;

    cudaFuncSetAttribute(rqs_flow_kernel,
                         cudaFuncAttributeMaxDynamicSharedMemorySize, (int)smemB);

    rqs_flow_kernel<<<grid, NTHREADS, smemB>>>(
        x, sc_scale, sc_shift, W_in, b_in, b1b, b2a, b2b,
        perms, (float*)d_out);
}